// round 11
// baseline (speedup 1.0000x reference)
#include <cuda_runtime.h>
#include <cuda_fp16.h>
#include <cstdint>

#define BB 8
#define NN 2048
#define FF 256
#define ALPHA 0.2f

// -------- scratch (device globals; no allocation allowed) --------
__device__ __half g_WhT[BB * FF * NN];        // 8 MB  (Wh^T, fp16)
__device__ __half g_WT_hi[FF * FF];           // W^T fp16 hi  [f][k]
__device__ __half g_WT_lo[FF * FF];           // W^T fp16 lo
__device__ float g_s1[BB * NN];
__device__ float g_s2[BB * NN];
__device__ float g_s2max[BB];

// ============================================================
// common helpers
// ============================================================
__device__ __forceinline__ void mma16816(float* c, const uint32_t* a, const uint32_t* b)
{
    asm volatile(
        "mma.sync.aligned.m16n8k16.row.col.f32.f16.f16.f32 "
        "{%0,%1,%2,%3}, {%4,%5,%6,%7}, {%8,%9}, {%0,%1,%2,%3};"
        : "+f"(c[0]), "+f"(c[1]), "+f"(c[2]), "+f"(c[3])
        : "r"(a[0]), "r"(a[1]), "r"(a[2]), "r"(a[3]), "r"(b[0]), "r"(b[1]));
}
__device__ __forceinline__ void ldsm_x4(uint32_t* r, uint32_t addr)
{
    asm volatile("ldmatrix.sync.aligned.m8n8.x4.shared.b16 {%0,%1,%2,%3}, [%4];"
        : "=r"(r[0]), "=r"(r[1]), "=r"(r[2]), "=r"(r[3]) : "r"(addr));
}
__device__ __forceinline__ uint32_t smem_u32(const void* p) {
    uint32_t a;
    asm("{ .reg .u64 t; cvta.to.shared.u64 t, %1; cvt.u32.u64 %0, t; }" : "=r"(a) : "l"(p));
    return a;
}
#define CP_ASYNC16(dst, src) asm volatile("cp.async.cg.shared.global [%0], [%1], 16;" :: "r"(dst), "l"(src) : "memory")
#define CP_COMMIT()  asm volatile("cp.async.commit_group;" ::: "memory")
#define CP_WAIT0()   asm volatile("cp.async.wait_group 0;" ::: "memory")
#define CP_WAIT1()   asm volatile("cp.async.wait_group 1;" ::: "memory")

#define VST 144   // smem row stride (64 fp16 + pad) -> conflict-free LDSM

// ============================================================
// Kernel 0: W [k][f] fp32 -> W^T hi/lo fp16 [f][k]
// ============================================================
__global__ __launch_bounds__(256) void prep_wt_kernel(const float* __restrict__ W)
{
    __shared__ float t[32][33];
    const int k0 = blockIdx.x * 32, f0 = blockIdx.y * 32;
    const int x = threadIdx.x & 31, y = threadIdx.x >> 5;
#pragma unroll
    for (int r = 0; r < 4; r++)
        t[y * 4 + r][x] = W[(size_t)(k0 + y * 4 + r) * FF + f0 + x];
    __syncthreads();
#pragma unroll
    for (int r = 0; r < 4; r++) {
        const int f = f0 + y * 4 + r;
        float v = t[x][y * 4 + r];
        __half hi = __float2half_rn(v);
        g_WT_hi[(size_t)f * FF + k0 + x] = hi;
        g_WT_lo[(size_t)f * FF + k0 + x] = __float2half_rn(v - __half2float(hi));
    }
}

// ============================================================
// Kernel 1: fused Wh GEMM (split-fp16 3-pass mma) + s1/s2 + WhT fp16
// (unchanged)
// ============================================================
#define GS_BH 0
#define GS_BL (GS_BH + FF * VST)
#define GS_AH (GS_BL + FF * VST)
#define GS_AL (GS_AH + 64 * VST)
#define GS_S1P (GS_AL + 64 * VST)
#define GS_S2P (GS_S1P + 64 * 4)
#define GS_TOTAL (GS_S2P + 64 * 4)
#define TSTR 66

__global__ __launch_bounds__(256, 2) void gemm_fused_kernel(
    const float* __restrict__ h, const float* __restrict__ aVec)
{
    extern __shared__ char smem[];
    const uint32_t smem_base = smem_u32(smem);
    const int tid = threadIdx.x;
    const int wid = tid >> 5;
    const int lane = tid & 31;
    const int m0 = blockIdx.x * 64;
    const int b = m0 / NN;
    const int n_in_b = m0 - b * NN;

    const int m0w = (wid & 1) * 32;
    const int n0w = (wid >> 1) * 64;

    float acc[2][8][4];
#pragma unroll
    for (int mt = 0; mt < 2; mt++)
#pragma unroll
        for (int nt = 0; nt < 8; nt++)
#pragma unroll
            for (int q = 0; q < 4; q++) acc[mt][nt][q] = 0.f;

    const uint32_t a_off_h = smem_base + GS_AH
        + (uint32_t)(m0w + ((lane >> 3) & 1) * 8 + (lane & 7)) * VST
        + (uint32_t)(lane >> 4) * 16;
    const uint32_t a_off_l = a_off_h + (GS_AL - GS_AH);
    const uint32_t b_row = (uint32_t)(n0w + ((lane >> 4) & 1) * 8 + (lane & 7)) * VST
        + (uint32_t)((lane >> 3) & 1) * 16;

    for (int kt = 0; kt < 4; kt++) {
        const int k0 = kt * 64;
#pragma unroll
        for (int it = 0; it < 8; it++) {
            const int idx = tid + it * 256;
            const int f = idx >> 3;
            const int c = idx & 7;
            const uint32_t so = f * VST + c * 16;
            const size_t go = (size_t)f * FF + k0 + c * 8;
            CP_ASYNC16(smem_base + GS_BH + so, (const char*)(g_WT_hi + go));
            CP_ASYNC16(smem_base + GS_BL + so, (const char*)(g_WT_lo + go));
        }
        CP_COMMIT();
#pragma unroll
        for (int t = 0; t < 4; t++) {
            const int idx = tid + t * 256;
            const int row = idx >> 4;
            const int cg = (idx & 15) * 4;
            float4 v = *(const float4*)&h[(size_t)(m0 + row) * FF + k0 + cg];
            __half hx = __float2half_rn(v.x), hy = __float2half_rn(v.y);
            __half hz = __float2half_rn(v.z), hw = __float2half_rn(v.w);
            __half2 hA = __halves2half2(hx, hy), hB = __halves2half2(hz, hw);
            __half2 lA = __halves2half2(__float2half_rn(v.x - __half2float(hx)),
                                        __float2half_rn(v.y - __half2float(hy)));
            __half2 lB = __halves2half2(__float2half_rn(v.z - __half2float(hz)),
                                        __float2half_rn(v.w - __half2float(hw)));
            uint2 hv, lv;
            hv.x = *reinterpret_cast<uint32_t*>(&hA);
            hv.y = *reinterpret_cast<uint32_t*>(&hB);
            lv.x = *reinterpret_cast<uint32_t*>(&lA);
            lv.y = *reinterpret_cast<uint32_t*>(&lB);
            *(uint2*)(smem + GS_AH + row * VST + cg * 2) = hv;
            *(uint2*)(smem + GS_AL + row * VST + cg * 2) = lv;
        }
        CP_WAIT0();
        __syncthreads();

#pragma unroll
        for (int ks = 0; ks < 4; ks++) {
            const uint32_t kb = ks * 32;
            uint32_t ah[2][4], al[2][4];
            ldsm_x4(ah[0], a_off_h + kb);
            ldsm_x4(ah[1], a_off_h + 16 * VST + kb);
            ldsm_x4(al[0], a_off_l + kb);
            ldsm_x4(al[1], a_off_l + 16 * VST + kb);
#pragma unroll
            for (int ntp = 0; ntp < 4; ntp++) {
                const uint32_t bo = b_row + ntp * 16 * VST + kb;
                uint32_t bh[4], bl[4];
                ldsm_x4(bh, smem_base + GS_BH + bo);
                ldsm_x4(bl, smem_base + GS_BL + bo);
#pragma unroll
                for (int mt = 0; mt < 2; mt++) {
                    mma16816(acc[mt][ntp * 2 + 0], ah[mt], &bh[0]);
                    mma16816(acc[mt][ntp * 2 + 1], ah[mt], &bh[2]);
                    mma16816(acc[mt][ntp * 2 + 0], ah[mt], &bl[0]);
                    mma16816(acc[mt][ntp * 2 + 1], ah[mt], &bl[2]);
                    mma16816(acc[mt][ntp * 2 + 0], al[mt], &bh[0]);
                    mma16816(acc[mt][ntp * 2 + 1], al[mt], &bh[2]);
                }
            }
        }
        __syncthreads();
    }

    const int ldq = lane >> 2;
    float* st = (float*)smem;
    float* s1p = (float*)(smem + GS_S1P);
    float* s2p = (float*)(smem + GS_S2P);

    if (tid < 64) { s1p[tid] = 0.f; s2p[tid] = 0.f; }
#pragma unroll
    for (int mt = 0; mt < 2; mt++) {
        const int r0 = m0w + mt * 16 + ldq;
#pragma unroll
        for (int nt = 0; nt < 8; nt++) {
            const int c0 = n0w + nt * 8 + (lane & 3) * 2;
            st[(c0 + 0) * TSTR + r0] = acc[mt][nt][0];
            st[(c0 + 1) * TSTR + r0] = acc[mt][nt][1];
            st[(c0 + 0) * TSTR + r0 + 8] = acc[mt][nt][2];
            st[(c0 + 1) * TSTR + r0 + 8] = acc[mt][nt][3];
        }
    }
    __syncthreads();

#pragma unroll
    for (int mt = 0; mt < 2; mt++) {
        const int r0 = m0w + mt * 16 + ldq;
        float s1x = 0.f, s1y = 0.f, s2x = 0.f, s2y = 0.f;
#pragma unroll
        for (int nt = 0; nt < 8; nt++) {
            const int c0 = n0w + nt * 8 + (lane & 3) * 2;
            float a10 = aVec[c0], a11 = aVec[c0 + 1];
            float a20 = aVec[FF + c0], a21 = aVec[FF + c0 + 1];
            s1x += acc[mt][nt][0] * a10 + acc[mt][nt][1] * a11;
            s1y += acc[mt][nt][2] * a10 + acc[mt][nt][3] * a11;
            s2x += acc[mt][nt][0] * a20 + acc[mt][nt][1] * a21;
            s2y += acc[mt][nt][2] * a20 + acc[mt][nt][3] * a21;
        }
#pragma unroll
        for (int o = 1; o <= 2; o <<= 1) {
            s1x += __shfl_xor_sync(0xffffffffu, s1x, o);
            s1y += __shfl_xor_sync(0xffffffffu, s1y, o);
            s2x += __shfl_xor_sync(0xffffffffu, s2x, o);
            s2y += __shfl_xor_sync(0xffffffffu, s2y, o);
        }
        if ((lane & 3) == 0) {
            atomicAdd(&s1p[r0], s1x);
            atomicAdd(&s1p[r0 + 8], s1y);
            atomicAdd(&s2p[r0], s2x);
            atomicAdd(&s2p[r0 + 8], s2y);
        }
    }
    __syncthreads();

    __half* whtB = g_WhT + (size_t)b * FF * NN + n_in_b;
#pragma unroll
    for (int t = 0; t < 16; t++) {
        const int idx = tid + t * 256;
        const int f = idx >> 4;
        const int m4 = (idx & 15) * 4;
        float v0 = st[f * TSTR + m4 + 0];
        float v1 = st[f * TSTR + m4 + 1];
        float v2 = st[f * TSTR + m4 + 2];
        float v3 = st[f * TSTR + m4 + 3];
        __half2 hA = __floats2half2_rn(v0, v1);
        __half2 hB = __floats2half2_rn(v2, v3);
        uint2 hv;
        hv.x = *reinterpret_cast<uint32_t*>(&hA);
        hv.y = *reinterpret_cast<uint32_t*>(&hB);
        *(uint2*)(whtB + (size_t)f * NN + m4) = hv;
    }
    if (tid < 64) {
        g_s1[m0 + tid] = s1p[tid];
        g_s2[m0 + tid] = s2p[tid];
    }
}

// ============================================================
// Kernel 2: per-batch max of s2
// ============================================================
__global__ __launch_bounds__(256) void s2max_kernel()
{
    __shared__ float red[256];
    const int b = blockIdx.x;
    float m = -1e30f;
    for (int i = threadIdx.x; i < NN; i += 256) m = fmaxf(m, g_s2[b * NN + i]);
    red[threadIdx.x] = m;
    __syncthreads();
#pragma unroll
    for (int s = 128; s; s >>= 1) {
        if (threadIdx.x < s) red[threadIdx.x] = fmaxf(red[threadIdx.x], red[threadIdx.x + s]);
        __syncthreads();
    }
    if (threadIdx.x == 0) g_s2max[b] = red[0];
}

// ============================================================
// Kernel 3: fused masked softmax + PV, f-SPLIT for occupancy:
// CTA = 64 queries x 128 features (grid.z = 2 f-halves, 512 CTAs)
// 8 warps (2m x 4n), warp 32q x 32f; double-V, single-P (R9 schedule)
// ============================================================
#define TI 64
#define KJ 64
#define NJ (NN / KJ)
#define FH 128                              // features per CTA

#define SM_VH0 0
#define SM_VH1 (SM_VH0 + FH * VST)          // 18432
#define SM_P   (SM_VH1 + FH * VST)          // 36864
#define SM_ZS  (SM_P + TI * VST)            // 46080
#define SM_TOTAL (SM_ZS + TI * 4)           // 46336

__global__ __launch_bounds__(256, 3) void attn_mma_kernel(
    const int* __restrict__ adj, float* __restrict__ out)
{
    extern __shared__ char smem[];
    const uint32_t smem_base = smem_u32(smem);
    const int tid = threadIdx.x;
    const int wid = tid >> 5;
    const int lane = tid & 31;
    const int b = blockIdx.y;
    const int i0 = blockIdx.x * TI;
    const int f0 = blockIdx.z * FH;

    const int m0w = (wid & 1) * 32;
    const int n0w = (wid >> 1) * 32;     // 4 n-warps x 32f = 128

    // P-compute mapping: thread -> (row r, 16 j's at jbase)
    const int r = tid >> 2;
    const int jbase = (tid & 3) * 16;

    const float s1v = g_s1[b * NN + i0 + r];
    const float ms2 = g_s2max[b];
    const float tpre = s1v + ms2;
    const float mi = tpre > 0.f ? tpre : ALPHA * tpre;
    float zloc = 0.f;

    const int* __restrict__ adjR = adj + ((size_t)b * NN + i0 + r) * NN;
    const float* __restrict__ s2B = g_s2 + b * NN;
    const __half* __restrict__ wht = g_WhT + (size_t)b * FF * NN + (size_t)f0 * NN;

    float acc[2][4][4];
#pragma unroll
    for (int mt = 0; mt < 2; mt++)
#pragma unroll
        for (int nt = 0; nt < 4; nt++)
#pragma unroll
            for (int q = 0; q < 4; q++) acc[mt][nt][q] = 0.f;

    const uint32_t a_off = smem_base + SM_P
        + (uint32_t)(m0w + ((lane >> 3) & 1) * 8 + (lane & 7)) * VST
        + (uint32_t)(lane >> 4) * 16;
    const uint32_t b_row = (uint32_t)(n0w + ((lane >> 4) & 1) * 8 + (lane & 7)) * VST
        + (uint32_t)((lane >> 3) & 1) * 16;

    // V staging: 128 f-rows x 64 j fp16 = 1024 x 16B chunks -> 4/thread
    const int vf = tid >> 3;
    const int vc = tid & 7;

    // prologue: issue V[0], prefetch adj[0]
    {
#pragma unroll
        for (int it = 0; it < 4; it++) {
            const int f = vf + it * 32;
            const uint32_t so = f * VST + vc * 16;
            const size_t go = (size_t)f * NN + 0 + vc * 8;
            CP_ASYNC16(smem_base + SM_VH0 + so, (const char*)(wht + go));
        }
        CP_COMMIT();
    }
    int4 am_pf[4];
#pragma unroll
    for (int g = 0; g < 4; g++)
        am_pf[g] = *(const int4*)&adjR[jbase + g * 4];

    for (int jt = 0; jt < NJ; jt++) {
        const int j0 = jt * KJ;
        const uint32_t vh = (jt & 1) ? SM_VH1 : SM_VH0;
        const uint32_t vhn = (jt & 1) ? SM_VH0 : SM_VH1;

        // ---- compute P tile [64 x 64] fp16 ----
#pragma unroll
        for (int g = 0; g < 4; g++) {
            const int j = j0 + jbase + g * 4;
            int4 am = am_pf[g];
            float4 s2q = *(const float4*)&s2B[j];
            float p0, p1, p2, p3, ev;
            ev = s1v + s2q.x; ev = ev > 0.f ? ev : ALPHA * ev;
            p0 = (am.x > 0) ? __expf(ev - mi) : 0.f;
            ev = s1v + s2q.y; ev = ev > 0.f ? ev : ALPHA * ev;
            p1 = (am.y > 0) ? __expf(ev - mi) : 0.f;
            ev = s1v + s2q.z; ev = ev > 0.f ? ev : ALPHA * ev;
            p2 = (am.z > 0) ? __expf(ev - mi) : 0.f;
            ev = s1v + s2q.w; ev = ev > 0.f ? ev : ALPHA * ev;
            p3 = (am.w > 0) ? __expf(ev - mi) : 0.f;
            zloc += (p0 + p1) + (p2 + p3);

            __half2 hA = __floats2half2_rn(p0, p1);
            __half2 hB = __floats2half2_rn(p2, p3);
            uint2 hv;
            hv.x = *reinterpret_cast<uint32_t*>(&hA);
            hv.y = *reinterpret_cast<uint32_t*>(&hB);
            *(uint2*)(smem + SM_P + r * VST + (jbase + g * 4) * 2) = hv;
        }

        // ---- wait V[jt]; make P + V visible ----
        CP_WAIT0();
        __syncthreads();

        // ---- issue V[jt+1] into other buffer (covered by MMA below) ----
        if (jt + 1 < NJ) {
            const int jn = j0 + KJ;
#pragma unroll
            for (int it = 0; it < 4; it++) {
                const int f = vf + it * 32;
                const uint32_t so = f * VST + vc * 16;
                const size_t go = (size_t)f * NN + jn + vc * 8;
                CP_ASYNC16(smem_base + vhn + so, (const char*)(wht + go));
            }
            CP_COMMIT();
            // prefetch adj[jt+1] (latency spans MMA)
#pragma unroll
            for (int g = 0; g < 4; g++)
                am_pf[g] = *(const int4*)&adjR[jn + jbase + g * 4];
        }

        // ---- HMMA: acc += P * V ----
#pragma unroll
        for (int ks = 0; ks < 4; ks++) {
            const uint32_t kb = ks * 32;
            uint32_t ah[2][4];
            ldsm_x4(ah[0], a_off + kb);
            ldsm_x4(ah[1], a_off + 16 * VST + kb);
#pragma unroll
            for (int ntp = 0; ntp < 2; ntp++) {
                const uint32_t bo = b_row + ntp * 16 * VST + kb;
                uint32_t bh[4];
                ldsm_x4(bh, smem_base + vh + bo);
#pragma unroll
                for (int mt = 0; mt < 2; mt++) {
                    mma16816(acc[mt][ntp * 2 + 0], ah[mt], &bh[0]);
                    mma16816(acc[mt][ntp * 2 + 1], ah[mt], &bh[2]);
                }
            }
        }
        __syncthreads();   // P buffer + V[jt] buffer reusable
    }

    // ---- Z reduction (quads share a row) ----
    zloc += __shfl_xor_sync(0xffffffffu, zloc, 1);
    zloc += __shfl_xor_sync(0xffffffffu, zloc, 2);
    if ((tid & 3) == 0) *(float*)(smem + SM_ZS + r * 4) = zloc;
    __syncthreads();

    // ---- epilogue: out = acc / Z ----
    const float* Zs = (const float*)(smem + SM_ZS);
    const int ldq = lane >> 2;
#pragma unroll
    for (int mt = 0; mt < 2; mt++) {
        const int row0 = m0w + mt * 16 + ldq;
        const float rz0 = 1.f / Zs[row0];
        const float rz1 = 1.f / Zs[row0 + 8];
        float* __restrict__ o0 = out + ((size_t)b * NN + i0 + row0) * FF + f0;
        float* __restrict__ o1 = o0 + 8 * FF;
#pragma unroll
        for (int nt = 0; nt < 4; nt++) {
            const int col = n0w + nt * 8 + (lane & 3) * 2;
            float2 v0 = make_float2(acc[mt][nt][0] * rz0, acc[mt][nt][1] * rz0);
            float2 v1 = make_float2(acc[mt][nt][2] * rz1, acc[mt][nt][3] * rz1);
            *(float2*)&o0[col] = v0;
            *(float2*)&o1[col] = v1;
        }
    }
}

// ============================================================
// launch
// ============================================================
extern "C" void kernel_launch(void* const* d_in, const int* in_sizes, int n_in,
                              void* d_out, int out_size)
{
    const float* h   = (const float*)d_in[0];
    const int*   adj = (const int*)d_in[1];
    const float* W   = (const float*)d_in[2];
    const float* a   = (const float*)d_in[3];
    float* out = (float*)d_out;

    cudaFuncSetAttribute(gemm_fused_kernel,
                         cudaFuncAttributeMaxDynamicSharedMemorySize, GS_TOTAL);
    cudaFuncSetAttribute(attn_mma_kernel,
                         cudaFuncAttributeMaxDynamicSharedMemorySize, SM_TOTAL);

    dim3 g0(FF / 32, FF / 32);
    prep_wt_kernel<<<g0, 256>>>(W);

    gemm_fused_kernel<<<BB * NN / 64, 256, GS_TOTAL>>>(h, a);

    s2max_kernel<<<BB, 256>>>();

    dim3 g4(NN / TI, BB, 2);
    attn_mma_kernel<<<g4, 256, SM_TOTAL>>>(adj, out);
}

// round 12
// speedup vs baseline: 1.7829x; 1.7829x over previous
#include <cuda_runtime.h>
#include <cuda_fp16.h>
#include <cstdint>

#define BB 8
#define NN 2048
#define FF 256
#define ALPHA 0.2f
#define LOG2E 1.4426950408889634f

// -------- scratch (device globals; no allocation allowed) --------
__device__ __half g_WhT[BB * FF * NN];        // 8 MB  (Wh^T, fp16)
__device__ __half g_WT_hi[FF * FF];           // W^T fp16 hi  [f][k]
__device__ __half g_WT_lo[FF * FF];           // W^T fp16 lo
__device__ float g_s1[BB * NN];               // pre-scaled by log2(e)
__device__ float g_s2[BB * NN];               // pre-scaled by log2(e)
__device__ float g_s2max[BB];

// ============================================================
// common helpers
// ============================================================
__device__ __forceinline__ void mma16816(float* c, const uint32_t* a, const uint32_t* b)
{
    asm volatile(
        "mma.sync.aligned.m16n8k16.row.col.f32.f16.f16.f32 "
        "{%0,%1,%2,%3}, {%4,%5,%6,%7}, {%8,%9}, {%0,%1,%2,%3};"
        : "+f"(c[0]), "+f"(c[1]), "+f"(c[2]), "+f"(c[3])
        : "r"(a[0]), "r"(a[1]), "r"(a[2]), "r"(a[3]), "r"(b[0]), "r"(b[1]));
}
__device__ __forceinline__ void ldsm_x4(uint32_t* r, uint32_t addr)
{
    asm volatile("ldmatrix.sync.aligned.m8n8.x4.shared.b16 {%0,%1,%2,%3}, [%4];"
        : "=r"(r[0]), "=r"(r[1]), "=r"(r[2]), "=r"(r[3]) : "r"(addr));
}
__device__ __forceinline__ uint32_t smem_u32(const void* p) {
    uint32_t a;
    asm("{ .reg .u64 t; cvta.to.shared.u64 t, %1; cvt.u32.u64 %0, t; }" : "=r"(a) : "l"(p));
    return a;
}
__device__ __forceinline__ float ex2f(float x) {
    float r;
    asm("ex2.approx.f32 %0, %1;" : "=f"(r) : "f"(x));
    return r;
}
#define CP_ASYNC16(dst, src) asm volatile("cp.async.cg.shared.global [%0], [%1], 16;" :: "r"(dst), "l"(src) : "memory")
#define CP_COMMIT()  asm volatile("cp.async.commit_group;" ::: "memory")
#define CP_WAIT0()   asm volatile("cp.async.wait_group 0;" ::: "memory")

#define VST 144   // smem row stride (64 fp16 + pad) -> conflict-free LDSM

// ============================================================
// Kernel 0: W [k][f] fp32 -> W^T hi/lo fp16 [f][k]
// ============================================================
__global__ __launch_bounds__(256) void prep_wt_kernel(const float* __restrict__ W)
{
    __shared__ float t[32][33];
    const int k0 = blockIdx.x * 32, f0 = blockIdx.y * 32;
    const int x = threadIdx.x & 31, y = threadIdx.x >> 5;
#pragma unroll
    for (int r = 0; r < 4; r++)
        t[y * 4 + r][x] = W[(size_t)(k0 + y * 4 + r) * FF + f0 + x];
    __syncthreads();
#pragma unroll
    for (int r = 0; r < 4; r++) {
        const int f = f0 + y * 4 + r;
        float v = t[x][y * 4 + r];
        __half hi = __float2half_rn(v);
        g_WT_hi[(size_t)f * FF + k0 + x] = hi;
        g_WT_lo[(size_t)f * FF + k0 + x] = __float2half_rn(v - __half2float(hi));
    }
}

// ============================================================
// Kernel 1: fused Wh GEMM (split-fp16 3-pass mma) + s1/s2 + WhT fp16
// ============================================================
#define GS_BH 0
#define GS_BL (GS_BH + FF * VST)
#define GS_AH (GS_BL + FF * VST)
#define GS_AL (GS_AH + 64 * VST)
#define GS_S1P (GS_AL + 64 * VST)
#define GS_S2P (GS_S1P + 64 * 4)
#define GS_TOTAL (GS_S2P + 64 * 4)
#define TSTR 66

__global__ __launch_bounds__(256, 2) void gemm_fused_kernel(
    const float* __restrict__ h, const float* __restrict__ aVec)
{
    extern __shared__ char smem[];
    const uint32_t smem_base = smem_u32(smem);
    const int tid = threadIdx.x;
    const int wid = tid >> 5;
    const int lane = tid & 31;
    const int m0 = blockIdx.x * 64;
    const int b = m0 / NN;
    const int n_in_b = m0 - b * NN;

    const int m0w = (wid & 1) * 32;
    const int n0w = (wid >> 1) * 64;

    float acc[2][8][4];
#pragma unroll
    for (int mt = 0; mt < 2; mt++)
#pragma unroll
        for (int nt = 0; nt < 8; nt++)
#pragma unroll
            for (int q = 0; q < 4; q++) acc[mt][nt][q] = 0.f;

    const uint32_t a_off_h = smem_base + GS_AH
        + (uint32_t)(m0w + ((lane >> 3) & 1) * 8 + (lane & 7)) * VST
        + (uint32_t)(lane >> 4) * 16;
    const uint32_t a_off_l = a_off_h + (GS_AL - GS_AH);
    const uint32_t b_row = (uint32_t)(n0w + ((lane >> 4) & 1) * 8 + (lane & 7)) * VST
        + (uint32_t)((lane >> 3) & 1) * 16;

    for (int kt = 0; kt < 4; kt++) {
        const int k0 = kt * 64;
#pragma unroll
        for (int it = 0; it < 8; it++) {
            const int idx = tid + it * 256;
            const int f = idx >> 3;
            const int c = idx & 7;
            const uint32_t so = f * VST + c * 16;
            const size_t go = (size_t)f * FF + k0 + c * 8;
            CP_ASYNC16(smem_base + GS_BH + so, (const char*)(g_WT_hi + go));
            CP_ASYNC16(smem_base + GS_BL + so, (const char*)(g_WT_lo + go));
        }
        CP_COMMIT();
#pragma unroll
        for (int t = 0; t < 4; t++) {
            const int idx = tid + t * 256;
            const int row = idx >> 4;
            const int cg = (idx & 15) * 4;
            float4 v = *(const float4*)&h[(size_t)(m0 + row) * FF + k0 + cg];
            __half hx = __float2half_rn(v.x), hy = __float2half_rn(v.y);
            __half hz = __float2half_rn(v.z), hw = __float2half_rn(v.w);
            __half2 hA = __halves2half2(hx, hy), hB = __halves2half2(hz, hw);
            __half2 lA = __halves2half2(__float2half_rn(v.x - __half2float(hx)),
                                        __float2half_rn(v.y - __half2float(hy)));
            __half2 lB = __halves2half2(__float2half_rn(v.z - __half2float(hz)),
                                        __float2half_rn(v.w - __half2float(hw)));
            uint2 hv, lv;
            hv.x = *reinterpret_cast<uint32_t*>(&hA);
            hv.y = *reinterpret_cast<uint32_t*>(&hB);
            lv.x = *reinterpret_cast<uint32_t*>(&lA);
            lv.y = *reinterpret_cast<uint32_t*>(&lB);
            *(uint2*)(smem + GS_AH + row * VST + cg * 2) = hv;
            *(uint2*)(smem + GS_AL + row * VST + cg * 2) = lv;
        }
        CP_WAIT0();
        __syncthreads();

#pragma unroll
        for (int ks = 0; ks < 4; ks++) {
            const uint32_t kb = ks * 32;
            uint32_t ah[2][4], al[2][4];
            ldsm_x4(ah[0], a_off_h + kb);
            ldsm_x4(ah[1], a_off_h + 16 * VST + kb);
            ldsm_x4(al[0], a_off_l + kb);
            ldsm_x4(al[1], a_off_l + 16 * VST + kb);
#pragma unroll
            for (int ntp = 0; ntp < 4; ntp++) {
                const uint32_t bo = b_row + ntp * 16 * VST + kb;
                uint32_t bh[4], bl[4];
                ldsm_x4(bh, smem_base + GS_BH + bo);
                ldsm_x4(bl, smem_base + GS_BL + bo);
#pragma unroll
                for (int mt = 0; mt < 2; mt++) {
                    mma16816(acc[mt][ntp * 2 + 0], ah[mt], &bh[0]);
                    mma16816(acc[mt][ntp * 2 + 1], ah[mt], &bh[2]);
                    mma16816(acc[mt][ntp * 2 + 0], ah[mt], &bl[0]);
                    mma16816(acc[mt][ntp * 2 + 1], ah[mt], &bl[2]);
                    mma16816(acc[mt][ntp * 2 + 0], al[mt], &bh[0]);
                    mma16816(acc[mt][ntp * 2 + 1], al[mt], &bh[2]);
                }
            }
        }
        __syncthreads();
    }

    const int ldq = lane >> 2;
    float* st = (float*)smem;
    float* s1p = (float*)(smem + GS_S1P);
    float* s2p = (float*)(smem + GS_S2P);

    if (tid < 64) { s1p[tid] = 0.f; s2p[tid] = 0.f; }
#pragma unroll
    for (int mt = 0; mt < 2; mt++) {
        const int r0 = m0w + mt * 16 + ldq;
#pragma unroll
        for (int nt = 0; nt < 8; nt++) {
            const int c0 = n0w + nt * 8 + (lane & 3) * 2;
            st[(c0 + 0) * TSTR + r0] = acc[mt][nt][0];
            st[(c0 + 1) * TSTR + r0] = acc[mt][nt][1];
            st[(c0 + 0) * TSTR + r0 + 8] = acc[mt][nt][2];
            st[(c0 + 1) * TSTR + r0 + 8] = acc[mt][nt][3];
        }
    }
    __syncthreads();

#pragma unroll
    for (int mt = 0; mt < 2; mt++) {
        const int r0 = m0w + mt * 16 + ldq;
        float s1x = 0.f, s1y = 0.f, s2x = 0.f, s2y = 0.f;
#pragma unroll
        for (int nt = 0; nt < 8; nt++) {
            const int c0 = n0w + nt * 8 + (lane & 3) * 2;
            float a10 = aVec[c0], a11 = aVec[c0 + 1];
            float a20 = aVec[FF + c0], a21 = aVec[FF + c0 + 1];
            s1x += acc[mt][nt][0] * a10 + acc[mt][nt][1] * a11;
            s1y += acc[mt][nt][2] * a10 + acc[mt][nt][3] * a11;
            s2x += acc[mt][nt][0] * a20 + acc[mt][nt][1] * a21;
            s2y += acc[mt][nt][2] * a20 + acc[mt][nt][3] * a21;
        }
#pragma unroll
        for (int o = 1; o <= 2; o <<= 1) {
            s1x += __shfl_xor_sync(0xffffffffu, s1x, o);
            s1y += __shfl_xor_sync(0xffffffffu, s1y, o);
            s2x += __shfl_xor_sync(0xffffffffu, s2x, o);
            s2y += __shfl_xor_sync(0xffffffffu, s2y, o);
        }
        if ((lane & 3) == 0) {
            atomicAdd(&s1p[r0], s1x);
            atomicAdd(&s1p[r0 + 8], s1y);
            atomicAdd(&s2p[r0], s2x);
            atomicAdd(&s2p[r0 + 8], s2y);
        }
    }
    __syncthreads();

    __half* whtB = g_WhT + (size_t)b * FF * NN + n_in_b;
#pragma unroll
    for (int t = 0; t < 16; t++) {
        const int idx = tid + t * 256;
        const int f = idx >> 4;
        const int m4 = (idx & 15) * 4;
        float v0 = st[f * TSTR + m4 + 0];
        float v1 = st[f * TSTR + m4 + 1];
        float v2 = st[f * TSTR + m4 + 2];
        float v3 = st[f * TSTR + m4 + 3];
        __half2 hA = __floats2half2_rn(v0, v1);
        __half2 hB = __floats2half2_rn(v2, v3);
        uint2 hv;
        hv.x = *reinterpret_cast<uint32_t*>(&hA);
        hv.y = *reinterpret_cast<uint32_t*>(&hB);
        *(uint2*)(whtB + (size_t)f * NN + m4) = hv;
    }
    if (tid < 64) {
        // pre-scale by log2(e): lrelu is positive-homogeneous, so exp(x)=exp2(x*log2e)
        g_s1[m0 + tid] = s1p[tid] * LOG2E;
        g_s2[m0 + tid] = s2p[tid] * LOG2E;
    }
}

// ============================================================
// Kernel 2: per-batch max of s2 (prescaled; log2e>0 keeps argmax)
// ============================================================
__global__ __launch_bounds__(256) void s2max_kernel()
{
    __shared__ float red[256];
    const int b = blockIdx.x;
    float m = -1e30f;
    for (int i = threadIdx.x; i < NN; i += 256) m = fmaxf(m, g_s2[b * NN + i]);
    red[threadIdx.x] = m;
    __syncthreads();
#pragma unroll
    for (int s = 128; s; s >>= 1) {
        if (threadIdx.x < s) red[threadIdx.x] = fmaxf(red[threadIdx.x], red[threadIdx.x + s]);
        __syncthreads();
    }
    if (threadIdx.x == 0) g_s2max[b] = red[0];
}

// ============================================================
// Kernel 3: fused masked softmax + PV, fp16 single-pass V,
// TI=64, KJ=64, V double-buffered (R9 schedule), 2 CTAs/SM
// P uses ex2.approx on prescaled logits
// ============================================================
#define TI 64
#define KJ 64
#define NJ (NN / KJ)

#define SM_VH0 0
#define SM_VH1 (SM_VH0 + FF * VST)          // 36864
#define SM_P   (SM_VH1 + FF * VST)          // 73728
#define SM_ZS  (SM_P + TI * VST)            // 82944
#define SM_TOTAL (SM_ZS + TI * 4)           // 83200

__global__ __launch_bounds__(256, 2) void attn_mma_kernel(
    const int* __restrict__ adj, float* __restrict__ out)
{
    extern __shared__ char smem[];
    const uint32_t smem_base = smem_u32(smem);
    const int tid = threadIdx.x;
    const int wid = tid >> 5;
    const int lane = tid & 31;
    const int b = blockIdx.y;
    const int i0 = blockIdx.x * TI;

    const int m0w = (wid & 1) * 32;
    const int n0w = (wid >> 1) * 64;

    // P-compute mapping: thread -> (row r, 16 j's at jbase)
    const int r = tid >> 2;
    const int jbase = (tid & 3) * 16;

    const float s1v = g_s1[b * NN + i0 + r];
    const float ms2 = g_s2max[b];
    const float tpre = s1v + ms2;
    const float mi = fmaxf(tpre, ALPHA * tpre);
    float zloc = 0.f;

    const int* __restrict__ adjR = adj + ((size_t)b * NN + i0 + r) * NN;
    const float* __restrict__ s2B = g_s2 + b * NN;
    const __half* __restrict__ wht = g_WhT + (size_t)b * FF * NN;

    float acc[2][8][4];
#pragma unroll
    for (int mt = 0; mt < 2; mt++)
#pragma unroll
        for (int nt = 0; nt < 8; nt++)
#pragma unroll
            for (int q = 0; q < 4; q++) acc[mt][nt][q] = 0.f;

    const uint32_t a_off = smem_base + SM_P
        + (uint32_t)(m0w + ((lane >> 3) & 1) * 8 + (lane & 7)) * VST
        + (uint32_t)(lane >> 4) * 16;
    const uint32_t b_row = (uint32_t)(n0w + ((lane >> 4) & 1) * 8 + (lane & 7)) * VST
        + (uint32_t)((lane >> 3) & 1) * 16;

    // V staging: 256 f-rows x 64 j fp16 = 2048 x 16B chunks -> 8/thread
    const int vf = tid >> 3;
    const int vc = tid & 7;

    // prologue: issue V[0], prefetch adj[0]
    {
#pragma unroll
        for (int it = 0; it < 8; it++) {
            const int f = vf + it * 32;
            const uint32_t so = f * VST + vc * 16;
            const size_t go = (size_t)f * NN + 0 + vc * 8;
            CP_ASYNC16(smem_base + SM_VH0 + so, (const char*)(wht + go));
        }
        CP_COMMIT();
    }
    int4 am_pf[4];
#pragma unroll
    for (int g = 0; g < 4; g++)
        am_pf[g] = *(const int4*)&adjR[jbase + g * 4];

    for (int jt = 0; jt < NJ; jt++) {
        const int j0 = jt * KJ;
        const uint32_t vh = (jt & 1) ? SM_VH1 : SM_VH0;
        const uint32_t vhn = (jt & 1) ? SM_VH0 : SM_VH1;

        // ---- compute P tile [64 x 64] fp16 (ex2 on prescaled logits) ----
#pragma unroll
        for (int g = 0; g < 4; g++) {
            const int j = j0 + jbase + g * 4;
            int4 am = am_pf[g];
            float4 s2q = *(const float4*)&s2B[j];
            float e0 = s1v + s2q.x;
            float e1 = s1v + s2q.y;
            float e2 = s1v + s2q.z;
            float e3 = s1v + s2q.w;
            e0 = fmaxf(e0, ALPHA * e0);
            e1 = fmaxf(e1, ALPHA * e1);
            e2 = fmaxf(e2, ALPHA * e2);
            e3 = fmaxf(e3, ALPHA * e3);
            float p0 = (am.x > 0) ? ex2f(e0 - mi) : 0.f;
            float p1 = (am.y > 0) ? ex2f(e1 - mi) : 0.f;
            float p2 = (am.z > 0) ? ex2f(e2 - mi) : 0.f;
            float p3 = (am.w > 0) ? ex2f(e3 - mi) : 0.f;
            zloc += (p0 + p1) + (p2 + p3);

            __half2 hA = __floats2half2_rn(p0, p1);
            __half2 hB = __floats2half2_rn(p2, p3);
            uint2 hv;
            hv.x = *reinterpret_cast<uint32_t*>(&hA);
            hv.y = *reinterpret_cast<uint32_t*>(&hB);
            *(uint2*)(smem + SM_P + r * VST + (jbase + g * 4) * 2) = hv;
        }

        // ---- wait V[jt]; make P + V visible ----
        CP_WAIT0();
        __syncthreads();

        // ---- issue V[jt+1] into other buffer (covered by MMA below) ----
        if (jt + 1 < NJ) {
            const int jn = j0 + KJ;
#pragma unroll
            for (int it = 0; it < 8; it++) {
                const int f = vf + it * 32;
                const uint32_t so = f * VST + vc * 16;
                const size_t go = (size_t)f * NN + jn + vc * 8;
                CP_ASYNC16(smem_base + vhn + so, (const char*)(wht + go));
            }
            CP_COMMIT();
            // prefetch adj[jt+1] (latency spans MMA)
#pragma unroll
            for (int g = 0; g < 4; g++)
                am_pf[g] = *(const int4*)&adjR[jn + jbase + g * 4];
        }

        // ---- HMMA: acc += P * V ----
#pragma unroll
        for (int ks = 0; ks < 4; ks++) {
            const uint32_t kb = ks * 32;
            uint32_t ah[2][4];
            ldsm_x4(ah[0], a_off + kb);
            ldsm_x4(ah[1], a_off + 16 * VST + kb);
#pragma unroll
            for (int ntp = 0; ntp < 4; ntp++) {
                const uint32_t bo = b_row + ntp * 16 * VST + kb;
                uint32_t bh[4];
                ldsm_x4(bh, smem_base + vh + bo);
#pragma unroll
                for (int mt = 0; mt < 2; mt++) {
                    mma16816(acc[mt][ntp * 2 + 0], ah[mt], &bh[0]);
                    mma16816(acc[mt][ntp * 2 + 1], ah[mt], &bh[2]);
                }
            }
        }
        __syncthreads();   // P buffer + V[jt] buffer reusable
    }

    // ---- Z reduction (quads share a row) ----
    zloc += __shfl_xor_sync(0xffffffffu, zloc, 1);
    zloc += __shfl_xor_sync(0xffffffffu, zloc, 2);
    if ((tid & 3) == 0) *(float*)(smem + SM_ZS + r * 4) = zloc;
    __syncthreads();

    // ---- epilogue: out = acc / Z ----
    const float* Zs = (const float*)(smem + SM_ZS);
    const int ldq = lane >> 2;
#pragma unroll
    for (int mt = 0; mt < 2; mt++) {
        const int row0 = m0w + mt * 16 + ldq;
        const float rz0 = 1.f / Zs[row0];
        const float rz1 = 1.f / Zs[row0 + 8];
        float* __restrict__ o0 = out + ((size_t)b * NN + i0 + row0) * FF;
        float* __restrict__ o1 = o0 + 8 * FF;
#pragma unroll
        for (int nt = 0; nt < 8; nt++) {
            const int col = n0w + nt * 8 + (lane & 3) * 2;
            float2 v0 = make_float2(acc[mt][nt][0] * rz0, acc[mt][nt][1] * rz0);
            float2 v1 = make_float2(acc[mt][nt][2] * rz1, acc[mt][nt][3] * rz1);
            *(float2*)&o0[col] = v0;
            *(float2*)&o1[col] = v1;
        }
    }
}

// ============================================================
// launch
// ============================================================
extern "C" void kernel_launch(void* const* d_in, const int* in_sizes, int n_in,
                              void* d_out, int out_size)
{
    const float* h   = (const float*)d_in[0];
    const int*   adj = (const int*)d_in[1];
    const float* W   = (const float*)d_in[2];
    const float* a   = (const float*)d_in[3];
    float* out = (float*)d_out;

    cudaFuncSetAttribute(gemm_fused_kernel,
                         cudaFuncAttributeMaxDynamicSharedMemorySize, GS_TOTAL);
    cudaFuncSetAttribute(attn_mma_kernel,
                         cudaFuncAttributeMaxDynamicSharedMemorySize, SM_TOTAL);

    dim3 g0(FF / 32, FF / 32);
    prep_wt_kernel<<<g0, 256>>>(W);

    gemm_fused_kernel<<<BB * NN / 64, 256, GS_TOTAL>>>(h, a);

    s2max_kernel<<<BB, 256>>>();

    dim3 g4(NN / TI, BB);
    attn_mma_kernel<<<g4, 256, SM_TOTAL>>>(adj, out);
}

// round 13
// speedup vs baseline: 1.8197x; 1.0207x over previous
#include <cuda_runtime.h>
#include <cuda_fp16.h>
#include <cstdint>

#define BB 8
#define NN 2048
#define FF 256
#define ALPHA 0.2f
#define LOG2E 1.4426950408889634f

// -------- scratch (device globals; no allocation allowed) --------
__device__ __half g_WhT[BB * FF * NN];        // 8 MB  (Wh^T, fp16)
__device__ __half g_WT_hi[FF * FF];           // W^T fp16 hi  [f][k]
__device__ __half g_WT_lo[FF * FF];           // W^T fp16 lo
__device__ float g_s1[BB * NN];               // pre-scaled by log2(e)
__device__ float g_s2[BB * NN];               // pre-scaled by log2(e)
__device__ unsigned int g_s2maxu[BB];         // ordered-uint encoded max

// ============================================================
// common helpers
// ============================================================
__device__ __forceinline__ void mma16816(float* c, const uint32_t* a, const uint32_t* b)
{
    asm volatile(
        "mma.sync.aligned.m16n8k16.row.col.f32.f16.f16.f32 "
        "{%0,%1,%2,%3}, {%4,%5,%6,%7}, {%8,%9}, {%0,%1,%2,%3};"
        : "+f"(c[0]), "+f"(c[1]), "+f"(c[2]), "+f"(c[3])
        : "r"(a[0]), "r"(a[1]), "r"(a[2]), "r"(a[3]), "r"(b[0]), "r"(b[1]));
}
__device__ __forceinline__ void ldsm_x4(uint32_t* r, uint32_t addr)
{
    asm volatile("ldmatrix.sync.aligned.m8n8.x4.shared.b16 {%0,%1,%2,%3}, [%4];"
        : "=r"(r[0]), "=r"(r[1]), "=r"(r[2]), "=r"(r[3]) : "r"(addr));
}
__device__ __forceinline__ uint32_t smem_u32(const void* p) {
    uint32_t a;
    asm("{ .reg .u64 t; cvta.to.shared.u64 t, %1; cvt.u32.u64 %0, t; }" : "=r"(a) : "l"(p));
    return a;
}
__device__ __forceinline__ float ex2f(float x) {
    float r;
    asm("ex2.approx.f32 %0, %1;" : "=f"(r) : "f"(x));
    return r;
}
// monotone float <-> uint encoding for atomicMax over floats
__device__ __forceinline__ unsigned int f2ord(float f) {
    unsigned int u = __float_as_uint(f);
    return (u & 0x80000000u) ? ~u : (u | 0x80000000u);
}
__device__ __forceinline__ float ord2f(unsigned int u) {
    u = (u & 0x80000000u) ? (u ^ 0x80000000u) : ~u;
    return __uint_as_float(u);
}
#define CP_ASYNC16(dst, src) asm volatile("cp.async.cg.shared.global [%0], [%1], 16;" :: "r"(dst), "l"(src) : "memory")
#define CP_COMMIT()  asm volatile("cp.async.commit_group;" ::: "memory")
#define CP_WAIT0()   asm volatile("cp.async.wait_group 0;" ::: "memory")
#define CP_WAIT1()   asm volatile("cp.async.wait_group 1;" ::: "memory")

#define VST 144   // smem row stride (64 fp16 + pad) -> conflict-free LDSM

// ============================================================
// Kernel 0: W [k][f] fp32 -> W^T hi/lo fp16 [f][k]  (+ s2max init)
// ============================================================
__global__ __launch_bounds__(256) void prep_wt_kernel(const float* __restrict__ W)
{
    __shared__ float t[32][33];
    if (blockIdx.x == 0 && blockIdx.y == 0 && threadIdx.x < BB)
        g_s2maxu[threadIdx.x] = f2ord(-3.0e38f);
    const int k0 = blockIdx.x * 32, f0 = blockIdx.y * 32;
    const int x = threadIdx.x & 31, y = threadIdx.x >> 5;
#pragma unroll
    for (int r = 0; r < 4; r++)
        t[y * 4 + r][x] = W[(size_t)(k0 + y * 4 + r) * FF + f0 + x];
    __syncthreads();
#pragma unroll
    for (int r = 0; r < 4; r++) {
        const int f = f0 + y * 4 + r;
        float v = t[x][y * 4 + r];
        __half hi = __float2half_rn(v);
        g_WT_hi[(size_t)f * FF + k0 + x] = hi;
        g_WT_lo[(size_t)f * FF + k0 + x] = __float2half_rn(v - __half2float(hi));
    }
}

// ============================================================
// Kernel 1: fused Wh GEMM (split-fp16 3-pass mma) + s1/s2 + s2max + WhT fp16
// ============================================================
#define GS_BH 0
#define GS_BL (GS_BH + FF * VST)
#define GS_AH (GS_BL + FF * VST)
#define GS_AL (GS_AH + 64 * VST)
#define GS_S1P (GS_AL + 64 * VST)
#define GS_S2P (GS_S1P + 64 * 4)
#define GS_TOTAL (GS_S2P + 64 * 4)
#define TSTR 66

__global__ __launch_bounds__(256, 2) void gemm_fused_kernel(
    const float* __restrict__ h, const float* __restrict__ aVec)
{
    extern __shared__ char smem[];
    const uint32_t smem_base = smem_u32(smem);
    const int tid = threadIdx.x;
    const int wid = tid >> 5;
    const int lane = tid & 31;
    const int m0 = blockIdx.x * 64;
    const int b = m0 / NN;
    const int n_in_b = m0 - b * NN;

    const int m0w = (wid & 1) * 32;
    const int n0w = (wid >> 1) * 64;

    float acc[2][8][4];
#pragma unroll
    for (int mt = 0; mt < 2; mt++)
#pragma unroll
        for (int nt = 0; nt < 8; nt++)
#pragma unroll
            for (int q = 0; q < 4; q++) acc[mt][nt][q] = 0.f;

    const uint32_t a_off_h = smem_base + GS_AH
        + (uint32_t)(m0w + ((lane >> 3) & 1) * 8 + (lane & 7)) * VST
        + (uint32_t)(lane >> 4) * 16;
    const uint32_t a_off_l = a_off_h + (GS_AL - GS_AH);
    const uint32_t b_row = (uint32_t)(n0w + ((lane >> 4) & 1) * 8 + (lane & 7)) * VST
        + (uint32_t)((lane >> 3) & 1) * 16;

    for (int kt = 0; kt < 4; kt++) {
        const int k0 = kt * 64;
#pragma unroll
        for (int it = 0; it < 8; it++) {
            const int idx = tid + it * 256;
            const int f = idx >> 3;
            const int c = idx & 7;
            const uint32_t so = f * VST + c * 16;
            const size_t go = (size_t)f * FF + k0 + c * 8;
            CP_ASYNC16(smem_base + GS_BH + so, (const char*)(g_WT_hi + go));
            CP_ASYNC16(smem_base + GS_BL + so, (const char*)(g_WT_lo + go));
        }
        CP_COMMIT();
#pragma unroll
        for (int t = 0; t < 4; t++) {
            const int idx = tid + t * 256;
            const int row = idx >> 4;
            const int cg = (idx & 15) * 4;
            float4 v = *(const float4*)&h[(size_t)(m0 + row) * FF + k0 + cg];
            __half hx = __float2half_rn(v.x), hy = __float2half_rn(v.y);
            __half hz = __float2half_rn(v.z), hw = __float2half_rn(v.w);
            __half2 hA = __halves2half2(hx, hy), hB = __halves2half2(hz, hw);
            __half2 lA = __halves2half2(__float2half_rn(v.x - __half2float(hx)),
                                        __float2half_rn(v.y - __half2float(hy)));
            __half2 lB = __halves2half2(__float2half_rn(v.z - __half2float(hz)),
                                        __float2half_rn(v.w - __half2float(hw)));
            uint2 hv, lv;
            hv.x = *reinterpret_cast<uint32_t*>(&hA);
            hv.y = *reinterpret_cast<uint32_t*>(&hB);
            lv.x = *reinterpret_cast<uint32_t*>(&lA);
            lv.y = *reinterpret_cast<uint32_t*>(&lB);
            *(uint2*)(smem + GS_AH + row * VST + cg * 2) = hv;
            *(uint2*)(smem + GS_AL + row * VST + cg * 2) = lv;
        }
        CP_WAIT0();
        __syncthreads();

#pragma unroll
        for (int ks = 0; ks < 4; ks++) {
            const uint32_t kb = ks * 32;
            uint32_t ah[2][4], al[2][4];
            ldsm_x4(ah[0], a_off_h + kb);
            ldsm_x4(ah[1], a_off_h + 16 * VST + kb);
            ldsm_x4(al[0], a_off_l + kb);
            ldsm_x4(al[1], a_off_l + 16 * VST + kb);
#pragma unroll
            for (int ntp = 0; ntp < 4; ntp++) {
                const uint32_t bo = b_row + ntp * 16 * VST + kb;
                uint32_t bh[4], bl[4];
                ldsm_x4(bh, smem_base + GS_BH + bo);
                ldsm_x4(bl, smem_base + GS_BL + bo);
#pragma unroll
                for (int mt = 0; mt < 2; mt++) {
                    mma16816(acc[mt][ntp * 2 + 0], ah[mt], &bh[0]);
                    mma16816(acc[mt][ntp * 2 + 1], ah[mt], &bh[2]);
                    mma16816(acc[mt][ntp * 2 + 0], ah[mt], &bl[0]);
                    mma16816(acc[mt][ntp * 2 + 1], ah[mt], &bl[2]);
                    mma16816(acc[mt][ntp * 2 + 0], al[mt], &bh[0]);
                    mma16816(acc[mt][ntp * 2 + 1], al[mt], &bh[2]);
                }
            }
        }
        __syncthreads();
    }

    const int ldq = lane >> 2;
    float* st = (float*)smem;
    float* s1p = (float*)(smem + GS_S1P);
    float* s2p = (float*)(smem + GS_S2P);

    if (tid < 64) { s1p[tid] = 0.f; s2p[tid] = 0.f; }
#pragma unroll
    for (int mt = 0; mt < 2; mt++) {
        const int r0 = m0w + mt * 16 + ldq;
#pragma unroll
        for (int nt = 0; nt < 8; nt++) {
            const int c0 = n0w + nt * 8 + (lane & 3) * 2;
            st[(c0 + 0) * TSTR + r0] = acc[mt][nt][0];
            st[(c0 + 1) * TSTR + r0] = acc[mt][nt][1];
            st[(c0 + 0) * TSTR + r0 + 8] = acc[mt][nt][2];
            st[(c0 + 1) * TSTR + r0 + 8] = acc[mt][nt][3];
        }
    }
    __syncthreads();

#pragma unroll
    for (int mt = 0; mt < 2; mt++) {
        const int r0 = m0w + mt * 16 + ldq;
        float s1x = 0.f, s1y = 0.f, s2x = 0.f, s2y = 0.f;
#pragma unroll
        for (int nt = 0; nt < 8; nt++) {
            const int c0 = n0w + nt * 8 + (lane & 3) * 2;
            float a10 = aVec[c0], a11 = aVec[c0 + 1];
            float a20 = aVec[FF + c0], a21 = aVec[FF + c0 + 1];
            s1x += acc[mt][nt][0] * a10 + acc[mt][nt][1] * a11;
            s1y += acc[mt][nt][2] * a10 + acc[mt][nt][3] * a11;
            s2x += acc[mt][nt][0] * a20 + acc[mt][nt][1] * a21;
            s2y += acc[mt][nt][2] * a20 + acc[mt][nt][3] * a21;
        }
#pragma unroll
        for (int o = 1; o <= 2; o <<= 1) {
            s1x += __shfl_xor_sync(0xffffffffu, s1x, o);
            s1y += __shfl_xor_sync(0xffffffffu, s1y, o);
            s2x += __shfl_xor_sync(0xffffffffu, s2x, o);
            s2y += __shfl_xor_sync(0xffffffffu, s2y, o);
        }
        if ((lane & 3) == 0) {
            atomicAdd(&s1p[r0], s1x);
            atomicAdd(&s1p[r0 + 8], s1y);
            atomicAdd(&s2p[r0], s2x);
            atomicAdd(&s2p[r0 + 8], s2y);
        }
    }
    __syncthreads();

    __half* whtB = g_WhT + (size_t)b * FF * NN + n_in_b;
#pragma unroll
    for (int t = 0; t < 16; t++) {
        const int idx = tid + t * 256;
        const int f = idx >> 4;
        const int m4 = (idx & 15) * 4;
        float v0 = st[f * TSTR + m4 + 0];
        float v1 = st[f * TSTR + m4 + 1];
        float v2 = st[f * TSTR + m4 + 2];
        float v3 = st[f * TSTR + m4 + 3];
        __half2 hA = __floats2half2_rn(v0, v1);
        __half2 hB = __floats2half2_rn(v2, v3);
        uint2 hv;
        hv.x = *reinterpret_cast<uint32_t*>(&hA);
        hv.y = *reinterpret_cast<uint32_t*>(&hB);
        *(uint2*)(whtB + (size_t)f * NN + m4) = hv;
    }
    if (tid < 64) {
        float s1v = s1p[tid] * LOG2E;
        float s2v = s2p[tid] * LOG2E;
        g_s1[m0 + tid] = s1v;
        g_s2[m0 + tid] = s2v;
        atomicMax(&g_s2maxu[b], f2ord(s2v));   // fused per-batch max
    }
}

// ============================================================
// Kernel 2: fused masked softmax + PV, fp16 single-pass V,
// TI=64, KJ=64, double-buffered V and P, one barrier per tile,
// P[t+1]-compute interleaved into MMA[t] at k-step granularity
// ============================================================
#define TI 64
#define KJ 64
#define NJ (NN / KJ)

#define SM_VH0 0
#define SM_VH1 (SM_VH0 + FF * VST)          // 36864
#define SM_P0  (SM_VH1 + FF * VST)          // 73728
#define SM_P1  (SM_P0 + TI * VST)           // 82944
#define SM_ZS  (SM_P1 + TI * VST)           // 92160
#define SM_TOTAL (SM_ZS + TI * 4)           // 92416

__global__ __launch_bounds__(256, 2) void attn_mma_kernel(
    const int* __restrict__ adj, float* __restrict__ out)
{
    extern __shared__ char smem[];
    const uint32_t smem_base = smem_u32(smem);
    const int tid = threadIdx.x;
    const int wid = tid >> 5;
    const int lane = tid & 31;
    const int b = blockIdx.y;
    const int i0 = blockIdx.x * TI;

    const int m0w = (wid & 1) * 32;
    const int n0w = (wid >> 1) * 64;

    // P-compute mapping: thread -> (row r, 16 j's at jbase)
    const int r = tid >> 2;
    const int jbase = (tid & 3) * 16;

    const float s1v = g_s1[b * NN + i0 + r];
    const float ms2 = ord2f(g_s2maxu[b]);
    const float tpre = s1v + ms2;
    const float mi = fmaxf(tpre, ALPHA * tpre);
    float zloc = 0.f;

    const int* __restrict__ adjR = adj + ((size_t)b * NN + i0 + r) * NN;
    const float* __restrict__ s2B = g_s2 + b * NN;
    const __half* __restrict__ wht = g_WhT + (size_t)b * FF * NN;

    float acc[2][8][4];
#pragma unroll
    for (int mt = 0; mt < 2; mt++)
#pragma unroll
        for (int nt = 0; nt < 8; nt++)
#pragma unroll
            for (int q = 0; q < 4; q++) acc[mt][nt][q] = 0.f;

    const uint32_t a_row = (uint32_t)(m0w + ((lane >> 3) & 1) * 8 + (lane & 7)) * VST
        + (uint32_t)(lane >> 4) * 16;
    const uint32_t b_row = (uint32_t)(n0w + ((lane >> 4) & 1) * 8 + (lane & 7)) * VST
        + (uint32_t)((lane >> 3) & 1) * 16;

    // V staging: 256 f-rows x 64 j fp16 = 2048 x 16B chunks -> 8/thread
    const int vf = tid >> 3;
    const int vc = tid & 7;

#define V_ISSUE(JT, VB)                                                          \
    {                                                                            \
        const int jn = (JT) * KJ;                                                \
        _Pragma("unroll")                                                        \
        for (int it = 0; it < 8; it++) {                                         \
            const int f = vf + it * 32;                                          \
            const uint32_t so = f * VST + vc * 16;                               \
            const size_t go = (size_t)f * NN + jn + vc * 8;                      \
            CP_ASYNC16(smem_base + (VB) + so, (const char*)(wht + go));          \
        }                                                                        \
        CP_COMMIT();                                                             \
    }

#define P_COMPUTE_G(JT, G, PB)                                                   \
    {                                                                            \
        const int j = (JT) * KJ + jbase + (G) * 4;                               \
        int4 am = am_pf[G];                                                      \
        float4 s2q = *(const float4*)&s2B[j];                                    \
        float e0 = s1v + s2q.x;                                                  \
        float e1 = s1v + s2q.y;                                                  \
        float e2 = s1v + s2q.z;                                                  \
        float e3 = s1v + s2q.w;                                                  \
        e0 = fmaxf(e0, ALPHA * e0);                                              \
        e1 = fmaxf(e1, ALPHA * e1);                                              \
        e2 = fmaxf(e2, ALPHA * e2);                                              \
        e3 = fmaxf(e3, ALPHA * e3);                                              \
        float p0 = (am.x > 0) ? ex2f(e0 - mi) : 0.f;                             \
        float p1 = (am.y > 0) ? ex2f(e1 - mi) : 0.f;                             \
        float p2 = (am.z > 0) ? ex2f(e2 - mi) : 0.f;                             \
        float p3 = (am.w > 0) ? ex2f(e3 - mi) : 0.f;                             \
        zloc += (p0 + p1) + (p2 + p3);                                           \
        __half2 hA = __floats2half2_rn(p0, p1);                                  \
        __half2 hB = __floats2half2_rn(p2, p3);                                  \
        uint2 hv;                                                                \
        hv.x = *reinterpret_cast<uint32_t*>(&hA);                                \
        hv.y = *reinterpret_cast<uint32_t*>(&hB);                                \
        *(uint2*)(smem + (PB) + r * VST + (jbase + (G) * 4) * 2) = hv;           \
    }

    // ---- prologue: V[0] & V[1] in flight, P[0] computed, adj[1] prefetched ----
    int4 am_pf[4];
#pragma unroll
    for (int g = 0; g < 4; g++)
        am_pf[g] = *(const int4*)&adjR[jbase + g * 4];
    V_ISSUE(0, SM_VH0);
#pragma unroll
    for (int g = 0; g < 4; g++)
        P_COMPUTE_G(0, g, SM_P0);
    V_ISSUE(1, SM_VH1);
#pragma unroll
    for (int g = 0; g < 4; g++)
        am_pf[g] = *(const int4*)&adjR[KJ + jbase + g * 4];
    CP_WAIT1();            // V[0] complete (V[1] still pending)
    __syncthreads();

    for (int jt = 0; jt < NJ; jt++) {
        const uint32_t vh = (jt & 1) ? SM_VH1 : SM_VH0;
        const uint32_t pb = (jt & 1) ? SM_P1 : SM_P0;
        const uint32_t pbn = (jt & 1) ? SM_P0 : SM_P1;
        const bool more = (jt + 1 < NJ);

        // ---- MMA on tile jt with P[jt+1] group interleaved per k-step ----
#pragma unroll
        for (int ks = 0; ks < 4; ks++) {
            const uint32_t kb = ks * 32;
            uint32_t ah[2][4];
            ldsm_x4(ah[0], smem_base + pb + a_row + kb);
            ldsm_x4(ah[1], smem_base + pb + a_row + 16 * VST + kb);

            // independent work fills the LDSM->HMMA latency window
            if (more)
                P_COMPUTE_G(jt + 1, ks, pbn);

#pragma unroll
            for (int ntp = 0; ntp < 4; ntp++) {
                const uint32_t bo = b_row + ntp * 16 * VST + kb;
                uint32_t bh[4];
                ldsm_x4(bh, smem_base + vh + bo);
#pragma unroll
                for (int mt = 0; mt < 2; mt++) {
                    mma16816(acc[mt][ntp * 2 + 0], ah[mt], &bh[0]);
                    mma16816(acc[mt][ntp * 2 + 1], ah[mt], &bh[2]);
                }
            }
        }

        // ---- prefetch adj[t+2] ----
        if (jt + 2 < NJ) {
            const int jn2 = (jt + 2) * KJ;
#pragma unroll
            for (int g = 0; g < 4; g++)
                am_pf[g] = *(const int4*)&adjR[jn2 + jbase + g * 4];
        }

        // ---- wait V[t+1] (issued a full iteration ago), single barrier ----
        CP_WAIT0();
        __syncthreads();

        // ---- refill V[t]'s buffer with V[t+2] ----
        if (jt + 2 < NJ)
            V_ISSUE(jt + 2, vh);
    }

    // ---- Z reduction (quads share a row) ----
    zloc += __shfl_xor_sync(0xffffffffu, zloc, 1);
    zloc += __shfl_xor_sync(0xffffffffu, zloc, 2);
    if ((tid & 3) == 0) *(float*)(smem + SM_ZS + r * 4) = zloc;
    __syncthreads();

    // ---- epilogue: out = acc / Z ----
    const float* Zs = (const float*)(smem + SM_ZS);
    const int ldq = lane >> 2;
#pragma unroll
    for (int mt = 0; mt < 2; mt++) {
        const int row0 = m0w + mt * 16 + ldq;
        const float rz0 = 1.f / Zs[row0];
        const float rz1 = 1.f / Zs[row0 + 8];
        float* __restrict__ o0 = out + ((size_t)b * NN + i0 + row0) * FF;
        float* __restrict__ o1 = o0 + 8 * FF;
#pragma unroll
        for (int nt = 0; nt < 8; nt++) {
            const int col = n0w + nt * 8 + (lane & 3) * 2;
            float2 v0 = make_float2(acc[mt][nt][0] * rz0, acc[mt][nt][1] * rz0);
            float2 v1 = make_float2(acc[mt][nt][2] * rz1, acc[mt][nt][3] * rz1);
            *(float2*)&o0[col] = v0;
            *(float2*)&o1[col] = v1;
        }
    }
}

// ============================================================
// launch
// ============================================================
extern "C" void kernel_launch(void* const* d_in, const int* in_sizes, int n_in,
                              void* d_out, int out_size)
{
    const float* h   = (const float*)d_in[0];
    const int*   adj = (const int*)d_in[1];
    const float* W   = (const float*)d_in[2];
    const float* a   = (const float*)d_in[3];
    float* out = (float*)d_out;

    cudaFuncSetAttribute(gemm_fused_kernel,
                         cudaFuncAttributeMaxDynamicSharedMemorySize, GS_TOTAL);
    cudaFuncSetAttribute(attn_mma_kernel,
                         cudaFuncAttributeMaxDynamicSharedMemorySize, SM_TOTAL);

    dim3 g0(FF / 32, FF / 32);
    prep_wt_kernel<<<g0, 256>>>(W);

    gemm_fused_kernel<<<BB * NN / 64, 256, GS_TOTAL>>>(h, a);

    dim3 g4(NN / TI, BB);
    attn_mma_kernel<<<g4, 256, SM_TOTAL>>>(adj, out);
}

// round 14
// speedup vs baseline: 1.8768x; 1.0314x over previous
#include <cuda_runtime.h>
#include <cuda_fp16.h>
#include <cstdint>

#define BB 8
#define NN 2048
#define FF 256
#define ALPHA 0.2f
#define LOG2E 1.4426950408889634f

// -------- scratch (device globals; no allocation allowed) --------
__device__ __half g_WhT[BB * FF * NN];        // 8 MB  (Wh^T, fp16)
__device__ __half g_WT_hi[FF * FF];           // W^T fp16 hi  [f][k]
__device__ __half g_WT_lo[FF * FF];           // W^T fp16 lo
__device__ float g_s1[BB * NN];               // pre-scaled by log2(e)
__device__ float g_s2[BB * NN];               // pre-scaled by log2(e)
__device__ unsigned int g_s2maxu[BB];         // ordered-uint encoded max

// ============================================================
// common helpers
// ============================================================
__device__ __forceinline__ void mma16816(float* c, const uint32_t* a, const uint32_t* b)
{
    asm volatile(
        "mma.sync.aligned.m16n8k16.row.col.f32.f16.f16.f32 "
        "{%0,%1,%2,%3}, {%4,%5,%6,%7}, {%8,%9}, {%0,%1,%2,%3};"
        : "+f"(c[0]), "+f"(c[1]), "+f"(c[2]), "+f"(c[3])
        : "r"(a[0]), "r"(a[1]), "r"(a[2]), "r"(a[3]), "r"(b[0]), "r"(b[1]));
}
__device__ __forceinline__ void ldsm_x4(uint32_t* r, uint32_t addr)
{
    asm volatile("ldmatrix.sync.aligned.m8n8.x4.shared.b16 {%0,%1,%2,%3}, [%4];"
        : "=r"(r[0]), "=r"(r[1]), "=r"(r[2]), "=r"(r[3]) : "r"(addr));
}
__device__ __forceinline__ uint32_t smem_u32(const void* p) {
    uint32_t a;
    asm("{ .reg .u64 t; cvta.to.shared.u64 t, %1; cvt.u32.u64 %0, t; }" : "=r"(a) : "l"(p));
    return a;
}
__device__ __forceinline__ float ex2f(float x) {
    float r;
    asm("ex2.approx.f32 %0, %1;" : "=f"(r) : "f"(x));
    return r;
}
__device__ __forceinline__ unsigned int f2ord(float f) {
    unsigned int u = __float_as_uint(f);
    return (u & 0x80000000u) ? ~u : (u | 0x80000000u);
}
__device__ __forceinline__ float ord2f(unsigned int u) {
    u = (u & 0x80000000u) ? (u ^ 0x80000000u) : ~u;
    return __uint_as_float(u);
}
#define CP_ASYNC16(dst, src) asm volatile("cp.async.cg.shared.global [%0], [%1], 16;" :: "r"(dst), "l"(src) : "memory")
#define CP_COMMIT()  asm volatile("cp.async.commit_group;" ::: "memory")
#define CP_WAIT0()   asm volatile("cp.async.wait_group 0;" ::: "memory")
#define CP_WAIT1()   asm volatile("cp.async.wait_group 1;" ::: "memory")

#define VST 144   // smem row stride (64 fp16 + pad) -> conflict-free LDSM

// ============================================================
// Kernel 0: W [k][f] fp32 -> W^T hi/lo fp16 [f][k]  (+ s2max init)
// ============================================================
__global__ __launch_bounds__(256) void prep_wt_kernel(const float* __restrict__ W)
{
    __shared__ float t[32][33];
    if (blockIdx.x == 0 && blockIdx.y == 0 && threadIdx.x < BB)
        g_s2maxu[threadIdx.x] = f2ord(-3.0e38f);
    const int k0 = blockIdx.x * 32, f0 = blockIdx.y * 32;
    const int x = threadIdx.x & 31, y = threadIdx.x >> 5;
#pragma unroll
    for (int r = 0; r < 4; r++)
        t[y * 4 + r][x] = W[(size_t)(k0 + y * 4 + r) * FF + f0 + x];
    __syncthreads();
#pragma unroll
    for (int r = 0; r < 4; r++) {
        const int f = f0 + y * 4 + r;
        float v = t[x][y * 4 + r];
        __half hi = __float2half_rn(v);
        g_WT_hi[(size_t)f * FF + k0 + x] = hi;
        g_WT_lo[(size_t)f * FF + k0 + x] = __float2half_rn(v - __half2float(hi));
    }
}

// ============================================================
// Kernel 1: fused Wh GEMM (2-pass: Ah*Bh + Ah*Bl) + s1/s2 + s2max + WhT fp16
// A = h rounded to fp16 (error cancels in softmax for s1; ~3e-4 on s2 path)
// ============================================================
#define GS_BH 0
#define GS_BL (GS_BH + FF * VST)
#define GS_AH (GS_BL + FF * VST)
#define GS_S1P (GS_AH + 64 * VST)
#define GS_S2P (GS_S1P + 64 * 4)
#define GS_TOTAL (GS_S2P + 64 * 4)
#define TSTR 66

__global__ __launch_bounds__(256, 2) void gemm_fused_kernel(
    const float* __restrict__ h, const float* __restrict__ aVec)
{
    extern __shared__ char smem[];
    const uint32_t smem_base = smem_u32(smem);
    const int tid = threadIdx.x;
    const int wid = tid >> 5;
    const int lane = tid & 31;
    const int m0 = blockIdx.x * 64;
    const int b = m0 / NN;
    const int n_in_b = m0 - b * NN;

    const int m0w = (wid & 1) * 32;
    const int n0w = (wid >> 1) * 64;

    float acc[2][8][4];
#pragma unroll
    for (int mt = 0; mt < 2; mt++)
#pragma unroll
        for (int nt = 0; nt < 8; nt++)
#pragma unroll
            for (int q = 0; q < 4; q++) acc[mt][nt][q] = 0.f;

    const uint32_t a_off_h = smem_base + GS_AH
        + (uint32_t)(m0w + ((lane >> 3) & 1) * 8 + (lane & 7)) * VST
        + (uint32_t)(lane >> 4) * 16;
    const uint32_t b_row = (uint32_t)(n0w + ((lane >> 4) & 1) * 8 + (lane & 7)) * VST
        + (uint32_t)((lane >> 3) & 1) * 16;

    for (int kt = 0; kt < 4; kt++) {
        const int k0 = kt * 64;
#pragma unroll
        for (int it = 0; it < 8; it++) {
            const int idx = tid + it * 256;
            const int f = idx >> 3;
            const int c = idx & 7;
            const uint32_t so = f * VST + c * 16;
            const size_t go = (size_t)f * FF + k0 + c * 8;
            CP_ASYNC16(smem_base + GS_BH + so, (const char*)(g_WT_hi + go));
            CP_ASYNC16(smem_base + GS_BL + so, (const char*)(g_WT_lo + go));
        }
        CP_COMMIT();
#pragma unroll
        for (int t = 0; t < 4; t++) {
            const int idx = tid + t * 256;
            const int row = idx >> 4;
            const int cg = (idx & 15) * 4;
            float4 v = *(const float4*)&h[(size_t)(m0 + row) * FF + k0 + cg];
            __half2 hA = __floats2half2_rn(v.x, v.y);
            __half2 hB = __floats2half2_rn(v.z, v.w);
            uint2 hv;
            hv.x = *reinterpret_cast<uint32_t*>(&hA);
            hv.y = *reinterpret_cast<uint32_t*>(&hB);
            *(uint2*)(smem + GS_AH + row * VST + cg * 2) = hv;
        }
        CP_WAIT0();
        __syncthreads();

#pragma unroll
        for (int ks = 0; ks < 4; ks++) {
            const uint32_t kb = ks * 32;
            uint32_t ah[2][4];
            ldsm_x4(ah[0], a_off_h + kb);
            ldsm_x4(ah[1], a_off_h + 16 * VST + kb);
#pragma unroll
            for (int ntp = 0; ntp < 4; ntp++) {
                const uint32_t bo = b_row + ntp * 16 * VST + kb;
                uint32_t bh[4], bl[4];
                ldsm_x4(bh, smem_base + GS_BH + bo);
                ldsm_x4(bl, smem_base + GS_BL + bo);
#pragma unroll
                for (int mt = 0; mt < 2; mt++) {
                    mma16816(acc[mt][ntp * 2 + 0], ah[mt], &bh[0]);
                    mma16816(acc[mt][ntp * 2 + 1], ah[mt], &bh[2]);
                    mma16816(acc[mt][ntp * 2 + 0], ah[mt], &bl[0]);
                    mma16816(acc[mt][ntp * 2 + 1], ah[mt], &bl[2]);
                }
            }
        }
        __syncthreads();
    }

    const int ldq = lane >> 2;
    float* st = (float*)smem;
    float* s1p = (float*)(smem + GS_S1P);
    float* s2p = (float*)(smem + GS_S2P);

    if (tid < 64) { s1p[tid] = 0.f; s2p[tid] = 0.f; }
#pragma unroll
    for (int mt = 0; mt < 2; mt++) {
        const int r0 = m0w + mt * 16 + ldq;
#pragma unroll
        for (int nt = 0; nt < 8; nt++) {
            const int c0 = n0w + nt * 8 + (lane & 3) * 2;
            st[(c0 + 0) * TSTR + r0] = acc[mt][nt][0];
            st[(c0 + 1) * TSTR + r0] = acc[mt][nt][1];
            st[(c0 + 0) * TSTR + r0 + 8] = acc[mt][nt][2];
            st[(c0 + 1) * TSTR + r0 + 8] = acc[mt][nt][3];
        }
    }
    __syncthreads();

#pragma unroll
    for (int mt = 0; mt < 2; mt++) {
        const int r0 = m0w + mt * 16 + ldq;
        float s1x = 0.f, s1y = 0.f, s2x = 0.f, s2y = 0.f;
#pragma unroll
        for (int nt = 0; nt < 8; nt++) {
            const int c0 = n0w + nt * 8 + (lane & 3) * 2;
            float a10 = aVec[c0], a11 = aVec[c0 + 1];
            float a20 = aVec[FF + c0], a21 = aVec[FF + c0 + 1];
            s1x += acc[mt][nt][0] * a10 + acc[mt][nt][1] * a11;
            s1y += acc[mt][nt][2] * a10 + acc[mt][nt][3] * a11;
            s2x += acc[mt][nt][0] * a20 + acc[mt][nt][1] * a21;
            s2y += acc[mt][nt][2] * a20 + acc[mt][nt][3] * a21;
        }
#pragma unroll
        for (int o = 1; o <= 2; o <<= 1) {
            s1x += __shfl_xor_sync(0xffffffffu, s1x, o);
            s1y += __shfl_xor_sync(0xffffffffu, s1y, o);
            s2x += __shfl_xor_sync(0xffffffffu, s2x, o);
            s2y += __shfl_xor_sync(0xffffffffu, s2y, o);
        }
        if ((lane & 3) == 0) {
            atomicAdd(&s1p[r0], s1x);
            atomicAdd(&s1p[r0 + 8], s1y);
            atomicAdd(&s2p[r0], s2x);
            atomicAdd(&s2p[r0 + 8], s2y);
        }
    }
    __syncthreads();

    __half* whtB = g_WhT + (size_t)b * FF * NN + n_in_b;
#pragma unroll
    for (int t = 0; t < 16; t++) {
        const int idx = tid + t * 256;
        const int f = idx >> 4;
        const int m4 = (idx & 15) * 4;
        float v0 = st[f * TSTR + m4 + 0];
        float v1 = st[f * TSTR + m4 + 1];
        float v2 = st[f * TSTR + m4 + 2];
        float v3 = st[f * TSTR + m4 + 3];
        __half2 hA = __floats2half2_rn(v0, v1);
        __half2 hB = __floats2half2_rn(v2, v3);
        uint2 hv;
        hv.x = *reinterpret_cast<uint32_t*>(&hA);
        hv.y = *reinterpret_cast<uint32_t*>(&hB);
        *(uint2*)(whtB + (size_t)f * NN + m4) = hv;
    }
    if (tid < 64) {
        float s1v = s1p[tid] * LOG2E;
        float s2v = s2p[tid] * LOG2E;
        g_s1[m0 + tid] = s1v;
        g_s2[m0 + tid] = s2v;
        atomicMax(&g_s2maxu[b], f2ord(s2v));
    }
}

// ============================================================
// Kernel 2: fused masked softmax + PV, fp16 single-pass V,
// TI=64, KJ=64, double-buffered V & P, one barrier per tile,
// jt-loop UNROLLED x2 (compile-time buffer offsets),
// P[t+1] interleaved into MMA[t] per k-step
// ============================================================
#define TI 64
#define KJ 64
#define NJ (NN / KJ)

#define SM_VH0 0
#define SM_VH1 (SM_VH0 + FF * VST)          // 36864
#define SM_P0  (SM_VH1 + FF * VST)          // 73728
#define SM_P1  (SM_P0 + TI * VST)           // 82944
#define SM_ZS  (SM_P1 + TI * VST)           // 92160
#define SM_TOTAL (SM_ZS + TI * 4)           // 92416

__global__ __launch_bounds__(256, 2) void attn_mma_kernel(
    const int* __restrict__ adj, float* __restrict__ out)
{
    extern __shared__ char smem[];
    const uint32_t smem_base = smem_u32(smem);
    const int tid = threadIdx.x;
    const int wid = tid >> 5;
    const int lane = tid & 31;
    const int b = blockIdx.y;
    const int i0 = blockIdx.x * TI;

    const int m0w = (wid & 1) * 32;
    const int n0w = (wid >> 1) * 64;

    const int r = tid >> 2;
    const int jbase = (tid & 3) * 16;

    const float s1v = g_s1[b * NN + i0 + r];
    const float ms2 = ord2f(g_s2maxu[b]);
    const float tpre = s1v + ms2;
    const float mi = fmaxf(tpre, ALPHA * tpre);
    float zloc = 0.f;

    const int* __restrict__ adjR = adj + ((size_t)b * NN + i0 + r) * NN;
    const float* __restrict__ s2B = g_s2 + b * NN;
    const __half* __restrict__ wht = g_WhT + (size_t)b * FF * NN;

    float acc[2][8][4];
#pragma unroll
    for (int mt = 0; mt < 2; mt++)
#pragma unroll
        for (int nt = 0; nt < 8; nt++)
#pragma unroll
            for (int q = 0; q < 4; q++) acc[mt][nt][q] = 0.f;

    const uint32_t a_row = (uint32_t)(m0w + ((lane >> 3) & 1) * 8 + (lane & 7)) * VST
        + (uint32_t)(lane >> 4) * 16;
    const uint32_t b_row = (uint32_t)(n0w + ((lane >> 4) & 1) * 8 + (lane & 7)) * VST
        + (uint32_t)((lane >> 3) & 1) * 16;

    const int vf = tid >> 3;
    const int vc = tid & 7;

#define V_ISSUE(JT, VB)                                                          \
    {                                                                            \
        const int jn = (JT) * KJ;                                                \
        _Pragma("unroll")                                                        \
        for (int it = 0; it < 8; it++) {                                         \
            const int f = vf + it * 32;                                          \
            const uint32_t so = f * VST + vc * 16;                               \
            const size_t go = (size_t)f * NN + jn + vc * 8;                      \
            CP_ASYNC16(smem_base + (VB) + so, (const char*)(wht + go));          \
        }                                                                        \
        CP_COMMIT();                                                             \
    }

#define P_COMPUTE_G(JT, G, PB)                                                   \
    {                                                                            \
        const int j = (JT) * KJ + jbase + (G) * 4;                               \
        int4 am = am_pf[G];                                                      \
        float4 s2q = *(const float4*)&s2B[j];                                    \
        float e0 = s1v + s2q.x;                                                  \
        float e1 = s1v + s2q.y;                                                  \
        float e2 = s1v + s2q.z;                                                  \
        float e3 = s1v + s2q.w;                                                  \
        e0 = fmaxf(e0, ALPHA * e0);                                              \
        e1 = fmaxf(e1, ALPHA * e1);                                              \
        e2 = fmaxf(e2, ALPHA * e2);                                              \
        e3 = fmaxf(e3, ALPHA * e3);                                              \
        float p0 = (am.x > 0) ? ex2f(e0 - mi) : 0.f;                             \
        float p1 = (am.y > 0) ? ex2f(e1 - mi) : 0.f;                             \
        float p2 = (am.z > 0) ? ex2f(e2 - mi) : 0.f;                             \
        float p3 = (am.w > 0) ? ex2f(e3 - mi) : 0.f;                             \
        zloc += (p0 + p1) + (p2 + p3);                                           \
        __half2 hA = __floats2half2_rn(p0, p1);                                  \
        __half2 hB = __floats2half2_rn(p2, p3);                                  \
        uint2 hv;                                                                \
        hv.x = *reinterpret_cast<uint32_t*>(&hA);                                \
        hv.y = *reinterpret_cast<uint32_t*>(&hB);                                \
        *(uint2*)(smem + (PB) + r * VST + (jbase + (G) * 4) * 2) = hv;           \
    }

// One pipeline stage: MMA on (VH_CUR, PB_CUR), interleave P[jt+1] into PB_NXT,
// prefetch adj[jt+2], wait V[jt+1], barrier, refill VH_CUR with V[jt+2].
#define ATTN_STAGE(JT, VH_CUR, PB_CUR, PB_NXT)                                   \
    {                                                                            \
        const bool more = ((JT) + 1 < NJ);                                       \
        _Pragma("unroll")                                                        \
        for (int ks = 0; ks < 4; ks++) {                                         \
            const uint32_t kb = ks * 32;                                         \
            uint32_t ah[2][4];                                                   \
            ldsm_x4(ah[0], smem_base + (PB_CUR) + a_row + kb);                   \
            ldsm_x4(ah[1], smem_base + (PB_CUR) + a_row + 16 * VST + kb);        \
            if (more)                                                            \
                P_COMPUTE_G((JT) + 1, ks, PB_NXT);                               \
            _Pragma("unroll")                                                    \
            for (int ntp = 0; ntp < 4; ntp++) {                                  \
                const uint32_t bo = b_row + ntp * 16 * VST + kb;                 \
                uint32_t bh[4];                                                  \
                ldsm_x4(bh, smem_base + (VH_CUR) + bo);                          \
                _Pragma("unroll")                                                \
                for (int mt = 0; mt < 2; mt++) {                                 \
                    mma16816(acc[mt][ntp * 2 + 0], ah[mt], &bh[0]);              \
                    mma16816(acc[mt][ntp * 2 + 1], ah[mt], &bh[2]);              \
                }                                                                \
            }                                                                    \
        }                                                                        \
        if ((JT) + 2 < NJ) {                                                     \
            const int jn2 = ((JT) + 2) * KJ;                                     \
            _Pragma("unroll")                                                    \
            for (int g = 0; g < 4; g++)                                          \
                am_pf[g] = *(const int4*)&adjR[jn2 + jbase + g * 4];             \
        }                                                                        \
        CP_WAIT0();                                                              \
        __syncthreads();                                                         \
        if ((JT) + 2 < NJ)                                                       \
            V_ISSUE((JT) + 2, VH_CUR);                                           \
    }

    // ---- prologue: V[0] & V[1] in flight, P[0] computed, adj[1] prefetched ----
    int4 am_pf[4];
#pragma unroll
    for (int g = 0; g < 4; g++)
        am_pf[g] = *(const int4*)&adjR[jbase + g * 4];
    V_ISSUE(0, SM_VH0);
#pragma unroll
    for (int g = 0; g < 4; g++)
        P_COMPUTE_G(0, g, SM_P0);
    V_ISSUE(1, SM_VH1);
#pragma unroll
    for (int g = 0; g < 4; g++)
        am_pf[g] = *(const int4*)&adjR[KJ + jbase + g * 4];
    CP_WAIT1();
    __syncthreads();

    // ---- main loop unrolled x2: compile-time buffer offsets ----
    for (int jt = 0; jt < NJ; jt += 2) {
        ATTN_STAGE(jt,     SM_VH0, SM_P0, SM_P1);
        ATTN_STAGE(jt + 1, SM_VH1, SM_P1, SM_P0);
    }

    // ---- Z reduction (quads share a row) ----
    zloc += __shfl_xor_sync(0xffffffffu, zloc, 1);
    zloc += __shfl_xor_sync(0xffffffffu, zloc, 2);
    if ((tid & 3) == 0) *(float*)(smem + SM_ZS + r * 4) = zloc;
    __syncthreads();

    // ---- epilogue: out = acc / Z ----
    const float* Zs = (const float*)(smem + SM_ZS);
    const int ldq = lane >> 2;
#pragma unroll
    for (int mt = 0; mt < 2; mt++) {
        const int row0 = m0w + mt * 16 + ldq;
        const float rz0 = 1.f / Zs[row0];
        const float rz1 = 1.f / Zs[row0 + 8];
        float* __restrict__ o0 = out + ((size_t)b * NN + i0 + row0) * FF;
        float* __restrict__ o1 = o0 + 8 * FF;
#pragma unroll
        for (int nt = 0; nt < 8; nt++) {
            const int col = n0w + nt * 8 + (lane & 3) * 2;
            float2 v0 = make_float2(acc[mt][nt][0] * rz0, acc[mt][nt][1] * rz0);
            float2 v1 = make_float2(acc[mt][nt][2] * rz1, acc[mt][nt][3] * rz1);
            *(float2*)&o0[col] = v0;
            *(float2*)&o1[col] = v1;
        }
    }
}

// ============================================================
// launch
// ============================================================
extern "C" void kernel_launch(void* const* d_in, const int* in_sizes, int n_in,
                              void* d_out, int out_size)
{
    const float* h   = (const float*)d_in[0];
    const int*   adj = (const int*)d_in[1];
    const float* W   = (const float*)d_in[2];
    const float* a   = (const float*)d_in[3];
    float* out = (float*)d_out;

    cudaFuncSetAttribute(gemm_fused_kernel,
                         cudaFuncAttributeMaxDynamicSharedMemorySize, GS_TOTAL);
    cudaFuncSetAttribute(attn_mma_kernel,
                         cudaFuncAttributeMaxDynamicSharedMemorySize, SM_TOTAL);

    dim3 g0(FF / 32, FF / 32);
    prep_wt_kernel<<<g0, 256>>>(W);

    gemm_fused_kernel<<<BB * NN / 64, 256, GS_TOTAL>>>(h, a);

    dim3 g4(NN / TI, BB);
    attn_mma_kernel<<<g4, 256, SM_TOTAL>>>(adj, out);
}

// round 16
// speedup vs baseline: 1.9801x; 1.0550x over previous
#include <cuda_runtime.h>
#include <cuda_fp16.h>
#include <cstdint>

#define BB 8
#define NN 2048
#define FF 256
#define ALPHA 0.2f
#define LOG2E 1.4426950408889634f

// -------- scratch (device globals; no allocation allowed) --------
__device__ __half g_WhT[BB * FF * NN];        // 8 MB  (Wh^T, fp16)
__device__ __half g_WT[FF * FF];              // W^T fp16  [f][k]
__device__ float g_s1[BB * NN];               // pre-scaled by log2(e)
__device__ float g_s2[BB * NN];               // pre-scaled by log2(e)
__device__ unsigned int g_s2maxu[BB];         // ordered-uint encoded max

// ============================================================
// common helpers
// ============================================================
__device__ __forceinline__ void mma16816(float* c, const uint32_t* a, const uint32_t* b)
{
    asm volatile(
        "mma.sync.aligned.m16n8k16.row.col.f32.f16.f16.f32 "
        "{%0,%1,%2,%3}, {%4,%5,%6,%7}, {%8,%9}, {%0,%1,%2,%3};"
        : "+f"(c[0]), "+f"(c[1]), "+f"(c[2]), "+f"(c[3])
        : "r"(a[0]), "r"(a[1]), "r"(a[2]), "r"(a[3]), "r"(b[0]), "r"(b[1]));
}
__device__ __forceinline__ void ldsm_x4(uint32_t* r, uint32_t addr)
{
    asm volatile("ldmatrix.sync.aligned.m8n8.x4.shared.b16 {%0,%1,%2,%3}, [%4];"
        : "=r"(r[0]), "=r"(r[1]), "=r"(r[2]), "=r"(r[3]) : "r"(addr));
}
__device__ __forceinline__ uint32_t smem_u32(const void* p) {
    uint32_t a;
    asm("{ .reg .u64 t; cvta.to.shared.u64 t, %1; cvt.u32.u64 %0, t; }" : "=r"(a) : "l"(p));
    return a;
}
__device__ __forceinline__ float ex2f(float x) {
    float r;
    asm("ex2.approx.f32 %0, %1;" : "=f"(r) : "f"(x));
    return r;
}
__device__ __forceinline__ unsigned int f2ord(float f) {
    unsigned int u = __float_as_uint(f);
    return (u & 0x80000000u) ? ~u : (u | 0x80000000u);
}
__device__ __forceinline__ float ord2f(unsigned int u) {
    u = (u & 0x80000000u) ? (u ^ 0x80000000u) : ~u;
    return __uint_as_float(u);
}
#define CP_ASYNC16(dst, src) asm volatile("cp.async.cg.shared.global [%0], [%1], 16;" :: "r"(dst), "l"(src) : "memory")
#define CP_COMMIT()  asm volatile("cp.async.commit_group;" ::: "memory")
#define CP_WAIT0()   asm volatile("cp.async.wait_group 0;" ::: "memory")
#define CP_WAIT1()   asm volatile("cp.async.wait_group 1;" ::: "memory")

#define VST 144   // smem row stride (64 fp16 + pad) -> conflict-free LDSM

// ============================================================
// Kernel 0: W [k][f] fp32 -> W^T fp16 [f][k]  (+ s2max init)
// ============================================================
__global__ __launch_bounds__(256) void prep_wt_kernel(const float* __restrict__ W)
{
    __shared__ float t[32][33];
    if (blockIdx.x == 0 && blockIdx.y == 0 && threadIdx.x < BB)
        g_s2maxu[threadIdx.x] = f2ord(-3.0e38f);
    const int k0 = blockIdx.x * 32, f0 = blockIdx.y * 32;
    const int x = threadIdx.x & 31, y = threadIdx.x >> 5;
#pragma unroll
    for (int r = 0; r < 4; r++)
        t[y * 4 + r][x] = W[(size_t)(k0 + y * 4 + r) * FF + f0 + x];
    __syncthreads();
#pragma unroll
    for (int r = 0; r < 4; r++) {
        const int f = f0 + y * 4 + r;
        g_WT[(size_t)f * FF + k0 + x] = __float2half_rn(t[x][y * 4 + r]);
    }
}

// ============================================================
// Kernel 1: fused Wh GEMM (1-pass fp16) + s1/s2 + s2max + WhT fp16
// smem layout: mainloop buffers [0, 46080); epilogue staging overlay
// needs 256*TSTR*4 = 67584 B, so S1P/S2P live above it.
// ============================================================
#define GS_BH 0
#define GS_AH (GS_BH + FF * VST)             // 36864
#define TSTR 66
#define GS_STG_END (256 * TSTR * 4)          // 67584 (epilogue overlay from 0)
#define GS_S1P GS_STG_END                    // 67584
#define GS_S2P (GS_S1P + 64 * 4)             // 67840
#define GS_TOTAL (GS_S2P + 64 * 4)           // 68096

__global__ __launch_bounds__(256, 2) void gemm_fused_kernel(
    const float* __restrict__ h, const float* __restrict__ aVec)
{
    extern __shared__ char smem[];
    const uint32_t smem_base = smem_u32(smem);
    const int tid = threadIdx.x;
    const int wid = tid >> 5;
    const int lane = tid & 31;
    const int m0 = blockIdx.x * 64;
    const int b = m0 / NN;
    const int n_in_b = m0 - b * NN;

    const int m0w = (wid & 1) * 32;
    const int n0w = (wid >> 1) * 64;

    float acc[2][8][4];
#pragma unroll
    for (int mt = 0; mt < 2; mt++)
#pragma unroll
        for (int nt = 0; nt < 8; nt++)
#pragma unroll
            for (int q = 0; q < 4; q++) acc[mt][nt][q] = 0.f;

    const uint32_t a_off_h = smem_base + GS_AH
        + (uint32_t)(m0w + ((lane >> 3) & 1) * 8 + (lane & 7)) * VST
        + (uint32_t)(lane >> 4) * 16;
    const uint32_t b_row = (uint32_t)(n0w + ((lane >> 4) & 1) * 8 + (lane & 7)) * VST
        + (uint32_t)((lane >> 3) & 1) * 16;

    for (int kt = 0; kt < 4; kt++) {
        const int k0 = kt * 64;
#pragma unroll
        for (int it = 0; it < 8; it++) {
            const int idx = tid + it * 256;
            const int f = idx >> 3;
            const int c = idx & 7;
            const uint32_t so = f * VST + c * 16;
            const size_t go = (size_t)f * FF + k0 + c * 8;
            CP_ASYNC16(smem_base + GS_BH + so, (const char*)(g_WT + go));
        }
        CP_COMMIT();
#pragma unroll
        for (int t = 0; t < 4; t++) {
            const int idx = tid + t * 256;
            const int row = idx >> 4;
            const int cg = (idx & 15) * 4;
            float4 v = *(const float4*)&h[(size_t)(m0 + row) * FF + k0 + cg];
            __half2 hA = __floats2half2_rn(v.x, v.y);
            __half2 hB = __floats2half2_rn(v.z, v.w);
            uint2 hv;
            hv.x = *reinterpret_cast<uint32_t*>(&hA);
            hv.y = *reinterpret_cast<uint32_t*>(&hB);
            *(uint2*)(smem + GS_AH + row * VST + cg * 2) = hv;
        }
        CP_WAIT0();
        __syncthreads();

#pragma unroll
        for (int ks = 0; ks < 4; ks++) {
            const uint32_t kb = ks * 32;
            uint32_t ah[2][4];
            ldsm_x4(ah[0], a_off_h + kb);
            ldsm_x4(ah[1], a_off_h + 16 * VST + kb);
#pragma unroll
            for (int ntp = 0; ntp < 4; ntp++) {
                const uint32_t bo = b_row + ntp * 16 * VST + kb;
                uint32_t bh[4];
                ldsm_x4(bh, smem_base + GS_BH + bo);
#pragma unroll
                for (int mt = 0; mt < 2; mt++) {
                    mma16816(acc[mt][ntp * 2 + 0], ah[mt], &bh[0]);
                    mma16816(acc[mt][ntp * 2 + 1], ah[mt], &bh[2]);
                }
            }
        }
        __syncthreads();
    }

    const int ldq = lane >> 2;
    float* st = (float*)smem;                     // overlay [0, 67584)
    float* s1p = (float*)(smem + GS_S1P);
    float* s2p = (float*)(smem + GS_S2P);

    if (tid < 64) { s1p[tid] = 0.f; s2p[tid] = 0.f; }
#pragma unroll
    for (int mt = 0; mt < 2; mt++) {
        const int r0 = m0w + mt * 16 + ldq;
#pragma unroll
        for (int nt = 0; nt < 8; nt++) {
            const int c0 = n0w + nt * 8 + (lane & 3) * 2;
            st[(c0 + 0) * TSTR + r0] = acc[mt][nt][0];
            st[(c0 + 1) * TSTR + r0] = acc[mt][nt][1];
            st[(c0 + 0) * TSTR + r0 + 8] = acc[mt][nt][2];
            st[(c0 + 1) * TSTR + r0 + 8] = acc[mt][nt][3];
        }
    }
    __syncthreads();

#pragma unroll
    for (int mt = 0; mt < 2; mt++) {
        const int r0 = m0w + mt * 16 + ldq;
        float s1x = 0.f, s1y = 0.f, s2x = 0.f, s2y = 0.f;
#pragma unroll
        for (int nt = 0; nt < 8; nt++) {
            const int c0 = n0w + nt * 8 + (lane & 3) * 2;
            float a10 = aVec[c0], a11 = aVec[c0 + 1];
            float a20 = aVec[FF + c0], a21 = aVec[FF + c0 + 1];
            s1x += acc[mt][nt][0] * a10 + acc[mt][nt][1] * a11;
            s1y += acc[mt][nt][2] * a10 + acc[mt][nt][3] * a11;
            s2x += acc[mt][nt][0] * a20 + acc[mt][nt][1] * a21;
            s2y += acc[mt][nt][2] * a20 + acc[mt][nt][3] * a21;
        }
#pragma unroll
        for (int o = 1; o <= 2; o <<= 1) {
            s1x += __shfl_xor_sync(0xffffffffu, s1x, o);
            s1y += __shfl_xor_sync(0xffffffffu, s1y, o);
            s2x += __shfl_xor_sync(0xffffffffu, s2x, o);
            s2y += __shfl_xor_sync(0xffffffffu, s2y, o);
        }
        if ((lane & 3) == 0) {
            atomicAdd(&s1p[r0], s1x);
            atomicAdd(&s1p[r0 + 8], s1y);
            atomicAdd(&s2p[r0], s2x);
            atomicAdd(&s2p[r0 + 8], s2y);
        }
    }
    __syncthreads();

    __half* whtB = g_WhT + (size_t)b * FF * NN + n_in_b;
#pragma unroll
    for (int t = 0; t < 16; t++) {
        const int idx = tid + t * 256;
        const int f = idx >> 4;
        const int m4 = (idx & 15) * 4;
        float v0 = st[f * TSTR + m4 + 0];
        float v1 = st[f * TSTR + m4 + 1];
        float v2 = st[f * TSTR + m4 + 2];
        float v3 = st[f * TSTR + m4 + 3];
        __half2 hA = __floats2half2_rn(v0, v1);
        __half2 hB = __floats2half2_rn(v2, v3);
        uint2 hv;
        hv.x = *reinterpret_cast<uint32_t*>(&hA);
        hv.y = *reinterpret_cast<uint32_t*>(&hB);
        *(uint2*)(whtB + (size_t)f * NN + m4) = hv;
    }
    if (tid < 64) {
        float s1v = s1p[tid] * LOG2E;
        float s2v = s2p[tid] * LOG2E;
        g_s1[m0 + tid] = s1v;
        g_s2[m0 + tid] = s2v;
        atomicMax(&g_s2maxu[b], f2ord(s2v));
    }
}

// ============================================================
// Kernel 2: fused masked softmax + PV, fp16 single-pass V,
// TI=64, KJ=64, double-buffered V & P, one barrier per tile,
// jt-loop UNROLLED x2, P[t+1] interleaved into MMA[t] per k-step
// (unchanged from R14 best)
// ============================================================
#define TI 64
#define KJ 64
#define NJ (NN / KJ)

#define SM_VH0 0
#define SM_VH1 (SM_VH0 + FF * VST)          // 36864
#define SM_P0  (SM_VH1 + FF * VST)          // 73728
#define SM_P1  (SM_P0 + TI * VST)           // 82944
#define SM_ZS  (SM_P1 + TI * VST)           // 92160
#define SM_TOTAL (SM_ZS + TI * 4)           // 92416

__global__ __launch_bounds__(256, 2) void attn_mma_kernel(
    const int* __restrict__ adj, float* __restrict__ out)
{
    extern __shared__ char smem[];
    const uint32_t smem_base = smem_u32(smem);
    const int tid = threadIdx.x;
    const int wid = tid >> 5;
    const int lane = tid & 31;
    const int b = blockIdx.y;
    const int i0 = blockIdx.x * TI;

    const int m0w = (wid & 1) * 32;
    const int n0w = (wid >> 1) * 64;

    const int r = tid >> 2;
    const int jbase = (tid & 3) * 16;

    const float s1v = g_s1[b * NN + i0 + r];
    const float ms2 = ord2f(g_s2maxu[b]);
    const float tpre = s1v + ms2;
    const float mi = fmaxf(tpre, ALPHA * tpre);
    float zloc = 0.f;

    const int* __restrict__ adjR = adj + ((size_t)b * NN + i0 + r) * NN;
    const float* __restrict__ s2B = g_s2 + b * NN;
    const __half* __restrict__ wht = g_WhT + (size_t)b * FF * NN;

    float acc[2][8][4];
#pragma unroll
    for (int mt = 0; mt < 2; mt++)
#pragma unroll
        for (int nt = 0; nt < 8; nt++)
#pragma unroll
            for (int q = 0; q < 4; q++) acc[mt][nt][q] = 0.f;

    const uint32_t a_row = (uint32_t)(m0w + ((lane >> 3) & 1) * 8 + (lane & 7)) * VST
        + (uint32_t)(lane >> 4) * 16;
    const uint32_t b_row = (uint32_t)(n0w + ((lane >> 4) & 1) * 8 + (lane & 7)) * VST
        + (uint32_t)((lane >> 3) & 1) * 16;

    const int vf = tid >> 3;
    const int vc = tid & 7;

#define V_ISSUE(JT, VB)                                                          \
    {                                                                            \
        const int jn = (JT) * KJ;                                                \
        _Pragma("unroll")                                                        \
        for (int it = 0; it < 8; it++) {                                         \
            const int f = vf + it * 32;                                          \
            const uint32_t so = f * VST + vc * 16;                               \
            const size_t go = (size_t)f * NN + jn + vc * 8;                      \
            CP_ASYNC16(smem_base + (VB) + so, (const char*)(wht + go));          \
        }                                                                        \
        CP_COMMIT();                                                             \
    }

#define P_COMPUTE_G(JT, G, PB)                                                   \
    {                                                                            \
        const int j = (JT) * KJ + jbase + (G) * 4;                               \
        int4 am = am_pf[G];                                                      \
        float4 s2q = *(const float4*)&s2B[j];                                    \
        float e0 = s1v + s2q.x;                                                  \
        float e1 = s1v + s2q.y;                                                  \
        float e2 = s1v + s2q.z;                                                  \
        float e3 = s1v + s2q.w;                                                  \
        e0 = fmaxf(e0, ALPHA * e0);                                              \
        e1 = fmaxf(e1, ALPHA * e1);                                              \
        e2 = fmaxf(e2, ALPHA * e2);                                              \
        e3 = fmaxf(e3, ALPHA * e3);                                              \
        float p0 = (am.x > 0) ? ex2f(e0 - mi) : 0.f;                             \
        float p1 = (am.y > 0) ? ex2f(e1 - mi) : 0.f;                             \
        float p2 = (am.z > 0) ? ex2f(e2 - mi) : 0.f;                             \
        float p3 = (am.w > 0) ? ex2f(e3 - mi) : 0.f;                             \
        zloc += (p0 + p1) + (p2 + p3);                                           \
        __half2 hA = __floats2half2_rn(p0, p1);                                  \
        __half2 hB = __floats2half2_rn(p2, p3);                                  \
        uint2 hv;                                                                \
        hv.x = *reinterpret_cast<uint32_t*>(&hA);                                \
        hv.y = *reinterpret_cast<uint32_t*>(&hB);                                \
        *(uint2*)(smem + (PB) + r * VST + (jbase + (G) * 4) * 2) = hv;           \
    }

#define ATTN_STAGE(JT, VH_CUR, PB_CUR, PB_NXT)                                   \
    {                                                                            \
        const bool more = ((JT) + 1 < NJ);                                       \
        _Pragma("unroll")                                                        \
        for (int ks = 0; ks < 4; ks++) {                                         \
            const uint32_t kb = ks * 32;                                         \
            uint32_t ah[2][4];                                                   \
            ldsm_x4(ah[0], smem_base + (PB_CUR) + a_row + kb);                   \
            ldsm_x4(ah[1], smem_base + (PB_CUR) + a_row + 16 * VST + kb);        \
            if (more)                                                            \
                P_COMPUTE_G((JT) + 1, ks, PB_NXT);                               \
            _Pragma("unroll")                                                    \
            for (int ntp = 0; ntp < 4; ntp++) {                                  \
                const uint32_t bo = b_row + ntp * 16 * VST + kb;                 \
                uint32_t bh[4];                                                  \
                ldsm_x4(bh, smem_base + (VH_CUR) + bo);                          \
                _Pragma("unroll")                                                \
                for (int mt = 0; mt < 2; mt++) {                                 \
                    mma16816(acc[mt][ntp * 2 + 0], ah[mt], &bh[0]);              \
                    mma16816(acc[mt][ntp * 2 + 1], ah[mt], &bh[2]);              \
                }                                                                \
            }                                                                    \
        }                                                                        \
        if ((JT) + 2 < NJ) {                                                     \
            const int jn2 = ((JT) + 2) * KJ;                                     \
            _Pragma("unroll")                                                    \
            for (int g = 0; g < 4; g++)                                          \
                am_pf[g] = *(const int4*)&adjR[jn2 + jbase + g * 4];             \
        }                                                                        \
        CP_WAIT0();                                                              \
        __syncthreads();                                                         \
        if ((JT) + 2 < NJ)                                                       \
            V_ISSUE((JT) + 2, VH_CUR);                                           \
    }

    // ---- prologue ----
    int4 am_pf[4];
#pragma unroll
    for (int g = 0; g < 4; g++)
        am_pf[g] = *(const int4*)&adjR[jbase + g * 4];
    V_ISSUE(0, SM_VH0);
#pragma unroll
    for (int g = 0; g < 4; g++)
        P_COMPUTE_G(0, g, SM_P0);
    V_ISSUE(1, SM_VH1);
#pragma unroll
    for (int g = 0; g < 4; g++)
        am_pf[g] = *(const int4*)&adjR[KJ + jbase + g * 4];
    CP_WAIT1();
    __syncthreads();

    for (int jt = 0; jt < NJ; jt += 2) {
        ATTN_STAGE(jt,     SM_VH0, SM_P0, SM_P1);
        ATTN_STAGE(jt + 1, SM_VH1, SM_P1, SM_P0);
    }

    // ---- Z reduction ----
    zloc += __shfl_xor_sync(0xffffffffu, zloc, 1);
    zloc += __shfl_xor_sync(0xffffffffu, zloc, 2);
    if ((tid & 3) == 0) *(float*)(smem + SM_ZS + r * 4) = zloc;
    __syncthreads();

    // ---- epilogue: out = acc / Z ----
    const float* Zs = (const float*)(smem + SM_ZS);
    const int ldq = lane >> 2;
#pragma unroll
    for (int mt = 0; mt < 2; mt++) {
        const int row0 = m0w + mt * 16 + ldq;
        const float rz0 = 1.f / Zs[row0];
        const float rz1 = 1.f / Zs[row0 + 8];
        float* __restrict__ o0 = out + ((size_t)b * NN + i0 + row0) * FF;
        float* __restrict__ o1 = o0 + 8 * FF;
#pragma unroll
        for (int nt = 0; nt < 8; nt++) {
            const int col = n0w + nt * 8 + (lane & 3) * 2;
            float2 v0 = make_float2(acc[mt][nt][0] * rz0, acc[mt][nt][1] * rz0);
            float2 v1 = make_float2(acc[mt][nt][2] * rz1, acc[mt][nt][3] * rz1);
            *(float2*)&o0[col] = v0;
            *(float2*)&o1[col] = v1;
        }
    }
}

// ============================================================
// launch
// ============================================================
extern "C" void kernel_launch(void* const* d_in, const int* in_sizes, int n_in,
                              void* d_out, int out_size)
{
    const float* h   = (const float*)d_in[0];
    const int*   adj = (const int*)d_in[1];
    const float* W   = (const float*)d_in[2];
    const float* a   = (const float*)d_in[3];
    float* out = (float*)d_out;

    cudaFuncSetAttribute(gemm_fused_kernel,
                         cudaFuncAttributeMaxDynamicSharedMemorySize, GS_TOTAL);
    cudaFuncSetAttribute(attn_mma_kernel,
                         cudaFuncAttributeMaxDynamicSharedMemorySize, SM_TOTAL);

    dim3 g0(FF / 32, FF / 32);
    prep_wt_kernel<<<g0, 256>>>(W);

    gemm_fused_kernel<<<BB * NN / 64, 256, GS_TOTAL>>>(h, a);

    dim3 g4(NN / TI, BB);
    attn_mma_kernel<<<g4, 256, SM_TOTAL>>>(adj, out);
}

// round 17
// speedup vs baseline: 1.9813x; 1.0006x over previous
#include <cuda_runtime.h>
#include <cuda_fp16.h>
#include <cstdint>

#define BB 8
#define NN 2048
#define FF 256
#define ALPHA 0.2f
#define LOG2E 1.4426950408889634f

// -------- scratch (device globals; no allocation allowed) --------
__device__ __half g_WhT[BB * FF * NN];        // 8 MB  (Wh^T, fp16)
__device__ float g_s1[BB * NN];               // pre-scaled by log2(e)
__device__ float g_s2[BB * NN];               // pre-scaled by log2(e)
__device__ unsigned int g_s2maxu[BB] = {};    // ordered-uint max; 0 < ord(any finite float)

// ============================================================
// common helpers
// ============================================================
__device__ __forceinline__ void mma16816(float* c, const uint32_t* a, const uint32_t* b)
{
    asm volatile(
        "mma.sync.aligned.m16n8k16.row.col.f32.f16.f16.f32 "
        "{%0,%1,%2,%3}, {%4,%5,%6,%7}, {%8,%9}, {%0,%1,%2,%3};"
        : "+f"(c[0]), "+f"(c[1]), "+f"(c[2]), "+f"(c[3])
        : "r"(a[0]), "r"(a[1]), "r"(a[2]), "r"(a[3]), "r"(b[0]), "r"(b[1]));
}
__device__ __forceinline__ void ldsm_x4(uint32_t* r, uint32_t addr)
{
    asm volatile("ldmatrix.sync.aligned.m8n8.x4.shared.b16 {%0,%1,%2,%3}, [%4];"
        : "=r"(r[0]), "=r"(r[1]), "=r"(r[2]), "=r"(r[3]) : "r"(addr));
}
__device__ __forceinline__ void ldsm_x4_t(uint32_t* r, uint32_t addr)
{
    asm volatile("ldmatrix.sync.aligned.m8n8.x4.trans.shared.b16 {%0,%1,%2,%3}, [%4];"
        : "=r"(r[0]), "=r"(r[1]), "=r"(r[2]), "=r"(r[3]) : "r"(addr));
}
__device__ __forceinline__ uint32_t smem_u32(const void* p) {
    uint32_t a;
    asm("{ .reg .u64 t; cvta.to.shared.u64 t, %1; cvt.u32.u64 %0, t; }" : "=r"(a) : "l"(p));
    return a;
}
__device__ __forceinline__ float ex2f(float x) {
    float r;
    asm("ex2.approx.f32 %0, %1;" : "=f"(r) : "f"(x));
    return r;
}
__device__ __forceinline__ unsigned int f2ord(float f) {
    unsigned int u = __float_as_uint(f);
    return (u & 0x80000000u) ? ~u : (u | 0x80000000u);
}
__device__ __forceinline__ float ord2f(unsigned int u) {
    u = (u & 0x80000000u) ? (u ^ 0x80000000u) : ~u;
    return __uint_as_float(u);
}
#define CP_ASYNC16(dst, src) asm volatile("cp.async.cg.shared.global [%0], [%1], 16;" :: "r"(dst), "l"(src) : "memory")
#define CP_COMMIT()  asm volatile("cp.async.commit_group;" ::: "memory")
#define CP_WAIT0()   asm volatile("cp.async.wait_group 0;" ::: "memory")
#define CP_WAIT1()   asm volatile("cp.async.wait_group 1;" ::: "memory")

#define VST 144   // A/P/V smem row stride (64 fp16 + pad) -> conflict-free LDSM

// ============================================================
// Kernel 1: fused Wh GEMM (1-pass fp16, W converted in-kernel,
// B fragments via ldmatrix.trans) + s1/s2 + s2max + WhT fp16
// B smem: [64 k][256 f] fp16, row stride BST=528 (conflict-free)
// ============================================================
#define BST 528
#define GS_B  0                              // 64*528 = 33792
#define GS_AH 33792                          // + 64*144 = 9216 -> 43008
#define TSTR 66
#define GS_STG_END (256 * TSTR * 4)          // 67584 (epilogue overlay from 0)
#define GS_S1P GS_STG_END                    // 67584
#define GS_S2P (GS_S1P + 64 * 4)             // 67840
#define GS_TOTAL (GS_S2P + 64 * 4)           // 68096

__global__ __launch_bounds__(256, 2) void gemm_fused_kernel(
    const float* __restrict__ h, const float* __restrict__ W,
    const float* __restrict__ aVec)
{
    extern __shared__ char smem[];
    const uint32_t smem_base = smem_u32(smem);
    const int tid = threadIdx.x;
    const int wid = tid >> 5;
    const int lane = tid & 31;
    const int m0 = blockIdx.x * 64;
    const int b = m0 / NN;
    const int n_in_b = m0 - b * NN;

    const int m0w = (wid & 1) * 32;
    const int n0w = (wid >> 1) * 64;

    float acc[2][8][4];
#pragma unroll
    for (int mt = 0; mt < 2; mt++)
#pragma unroll
        for (int nt = 0; nt < 8; nt++)
#pragma unroll
            for (int q = 0; q < 4; q++) acc[mt][nt][q] = 0.f;

    const uint32_t a_off_h = smem_base + GS_AH
        + (uint32_t)(m0w + ((lane >> 3) & 1) * 8 + (lane & 7)) * VST
        + (uint32_t)(lane >> 4) * 16;
    // trans-LDSM per-lane base for B [k][f]: mat0/1 = k rows j, j+8; mat2/3 = f +8
    const uint32_t bt_row = (uint32_t)((lane & 7) + ((lane >> 3) & 1) * 8) * BST
        + (uint32_t)(lane >> 4) * 16 + (uint32_t)n0w * 2;

    // B staging mapping: warp-uniform k row, lane = f8 group
    const int bk_base = tid >> 5;            // warp id -> starting k row (advances by 8)
    const int bf8 = lane;                    // f8 group 0..31 (f = 8*lane)

    for (int kt = 0; kt < 4; kt++) {
        const int k0 = kt * 64;
        // ---- stage B: W[k0+k][f] fp32 -> fp16 smem [k][f], coalesced ----
#pragma unroll
        for (int it = 0; it < 8; it++) {
            const int k = bk_base + it * 8;
            const float* wrow = W + (size_t)(k0 + k) * FF + bf8 * 8;
            float4 v0 = *(const float4*)(wrow);
            float4 v1 = *(const float4*)(wrow + 4);
            __half2 h0 = __floats2half2_rn(v0.x, v0.y);
            __half2 h1 = __floats2half2_rn(v0.z, v0.w);
            __half2 h2 = __floats2half2_rn(v1.x, v1.y);
            __half2 h3 = __floats2half2_rn(v1.z, v1.w);
            uint4 pk;
            pk.x = *reinterpret_cast<uint32_t*>(&h0);
            pk.y = *reinterpret_cast<uint32_t*>(&h1);
            pk.z = *reinterpret_cast<uint32_t*>(&h2);
            pk.w = *reinterpret_cast<uint32_t*>(&h3);
            *(uint4*)(smem + GS_B + k * BST + bf8 * 16) = pk;
        }
        // ---- stage A: h tile fp32 -> fp16 smem [m][k] ----
#pragma unroll
        for (int t = 0; t < 4; t++) {
            const int idx = tid + t * 256;
            const int row = idx >> 4;
            const int cg = (idx & 15) * 4;
            float4 v = *(const float4*)&h[(size_t)(m0 + row) * FF + k0 + cg];
            __half2 hA = __floats2half2_rn(v.x, v.y);
            __half2 hB = __floats2half2_rn(v.z, v.w);
            uint2 hv;
            hv.x = *reinterpret_cast<uint32_t*>(&hA);
            hv.y = *reinterpret_cast<uint32_t*>(&hB);
            *(uint2*)(smem + GS_AH + row * VST + cg * 2) = hv;
        }
        __syncthreads();

#pragma unroll
        for (int ks = 0; ks < 4; ks++) {
            uint32_t ah[2][4];
            ldsm_x4(ah[0], a_off_h + ks * 32);
            ldsm_x4(ah[1], a_off_h + 16 * VST + ks * 32);
#pragma unroll
            for (int ntp = 0; ntp < 4; ntp++) {
                const uint32_t bo = bt_row + ks * 16 * BST + ntp * 32;
                uint32_t bh[4];
                ldsm_x4_t(bh, smem_base + GS_B + bo);
#pragma unroll
                for (int mt = 0; mt < 2; mt++) {
                    mma16816(acc[mt][ntp * 2 + 0], ah[mt], &bh[0]);
                    mma16816(acc[mt][ntp * 2 + 1], ah[mt], &bh[2]);
                }
            }
        }
        __syncthreads();
    }

    const int ldq = lane >> 2;
    float* st = (float*)smem;                     // overlay [0, 67584)
    float* s1p = (float*)(smem + GS_S1P);
    float* s2p = (float*)(smem + GS_S2P);

    if (tid < 64) { s1p[tid] = 0.f; s2p[tid] = 0.f; }
#pragma unroll
    for (int mt = 0; mt < 2; mt++) {
        const int r0 = m0w + mt * 16 + ldq;
#pragma unroll
        for (int nt = 0; nt < 8; nt++) {
            const int c0 = n0w + nt * 8 + (lane & 3) * 2;
            st[(c0 + 0) * TSTR + r0] = acc[mt][nt][0];
            st[(c0 + 1) * TSTR + r0] = acc[mt][nt][1];
            st[(c0 + 0) * TSTR + r0 + 8] = acc[mt][nt][2];
            st[(c0 + 1) * TSTR + r0 + 8] = acc[mt][nt][3];
        }
    }
    __syncthreads();

#pragma unroll
    for (int mt = 0; mt < 2; mt++) {
        const int r0 = m0w + mt * 16 + ldq;
        float s1x = 0.f, s1y = 0.f, s2x = 0.f, s2y = 0.f;
#pragma unroll
        for (int nt = 0; nt < 8; nt++) {
            const int c0 = n0w + nt * 8 + (lane & 3) * 2;
            float a10 = aVec[c0], a11 = aVec[c0 + 1];
            float a20 = aVec[FF + c0], a21 = aVec[FF + c0 + 1];
            s1x += acc[mt][nt][0] * a10 + acc[mt][nt][1] * a11;
            s1y += acc[mt][nt][2] * a10 + acc[mt][nt][3] * a11;
            s2x += acc[mt][nt][0] * a20 + acc[mt][nt][1] * a21;
            s2y += acc[mt][nt][2] * a20 + acc[mt][nt][3] * a21;
        }
#pragma unroll
        for (int o = 1; o <= 2; o <<= 1) {
            s1x += __shfl_xor_sync(0xffffffffu, s1x, o);
            s1y += __shfl_xor_sync(0xffffffffu, s1y, o);
            s2x += __shfl_xor_sync(0xffffffffu, s2x, o);
            s2y += __shfl_xor_sync(0xffffffffu, s2y, o);
        }
        if ((lane & 3) == 0) {
            atomicAdd(&s1p[r0], s1x);
            atomicAdd(&s1p[r0 + 8], s1y);
            atomicAdd(&s2p[r0], s2x);
            atomicAdd(&s2p[r0 + 8], s2y);
        }
    }
    __syncthreads();

    __half* whtB = g_WhT + (size_t)b * FF * NN + n_in_b;
#pragma unroll
    for (int t = 0; t < 16; t++) {
        const int idx = tid + t * 256;
        const int f = idx >> 4;
        const int m4 = (idx & 15) * 4;
        float v0 = st[f * TSTR + m4 + 0];
        float v1 = st[f * TSTR + m4 + 1];
        float v2 = st[f * TSTR + m4 + 2];
        float v3 = st[f * TSTR + m4 + 3];
        __half2 hA = __floats2half2_rn(v0, v1);
        __half2 hB = __floats2half2_rn(v2, v3);
        uint2 hv;
        hv.x = *reinterpret_cast<uint32_t*>(&hA);
        hv.y = *reinterpret_cast<uint32_t*>(&hB);
        *(uint2*)(whtB + (size_t)f * NN + m4) = hv;
    }
    if (tid < 64) {
        float s1v = s1p[tid] * LOG2E;
        float s2v = s2p[tid] * LOG2E;
        g_s1[m0 + tid] = s1v;
        g_s2[m0 + tid] = s2v;
        atomicMax(&g_s2maxu[b], f2ord(s2v));
    }
}

// ============================================================
// Kernel 2: fused masked softmax + PV  (frozen R16 structure)
// ============================================================
#define TI 64
#define KJ 64
#define NJ (NN / KJ)

#define SM_VH0 0
#define SM_VH1 (SM_VH0 + FF * VST)          // 36864
#define SM_P0  (SM_VH1 + FF * VST)          // 73728
#define SM_P1  (SM_P0 + TI * VST)           // 82944
#define SM_ZS  (SM_P1 + TI * VST)           // 92160
#define SM_TOTAL (SM_ZS + TI * 4)           // 92416

__global__ __launch_bounds__(256, 2) void attn_mma_kernel(
    const int* __restrict__ adj, float* __restrict__ out)
{
    extern __shared__ char smem[];
    const uint32_t smem_base = smem_u32(smem);
    const int tid = threadIdx.x;
    const int wid = tid >> 5;
    const int lane = tid & 31;
    const int b = blockIdx.y;
    const int i0 = blockIdx.x * TI;

    const int m0w = (wid & 1) * 32;
    const int n0w = (wid >> 1) * 64;

    const int r = tid >> 2;
    const int jbase = (tid & 3) * 16;

    const float s1v = g_s1[b * NN + i0 + r];
    const float ms2 = ord2f(g_s2maxu[b]);
    const float tpre = s1v + ms2;
    const float mi = fmaxf(tpre, ALPHA * tpre);
    float zloc = 0.f;

    const int* __restrict__ adjR = adj + ((size_t)b * NN + i0 + r) * NN;
    const float* __restrict__ s2B = g_s2 + b * NN;
    const __half* __restrict__ wht = g_WhT + (size_t)b * FF * NN;

    float acc[2][8][4];
#pragma unroll
    for (int mt = 0; mt < 2; mt++)
#pragma unroll
        for (int nt = 0; nt < 8; nt++)
#pragma unroll
            for (int q = 0; q < 4; q++) acc[mt][nt][q] = 0.f;

    const uint32_t a_row = (uint32_t)(m0w + ((lane >> 3) & 1) * 8 + (lane & 7)) * VST
        + (uint32_t)(lane >> 4) * 16;
    const uint32_t b_row = (uint32_t)(n0w + ((lane >> 4) & 1) * 8 + (lane & 7)) * VST
        + (uint32_t)((lane >> 3) & 1) * 16;

    const int vf = tid >> 3;
    const int vc = tid & 7;

#define V_ISSUE(JT, VB)                                                          \
    {                                                                            \
        const int jn = (JT) * KJ;                                                \
        _Pragma("unroll")                                                        \
        for (int it = 0; it < 8; it++) {                                         \
            const int f = vf + it * 32;                                          \
            const uint32_t so = f * VST + vc * 16;                               \
            const size_t go = (size_t)f * NN + jn + vc * 8;                      \
            CP_ASYNC16(smem_base + (VB) + so, (const char*)(wht + go));          \
        }                                                                        \
        CP_COMMIT();                                                             \
    }

#define P_COMPUTE_G(JT, G, PB)                                                   \
    {                                                                            \
        const int j = (JT) * KJ + jbase + (G) * 4;                               \
        int4 am = am_pf[G];                                                      \
        float4 s2q = *(const float4*)&s2B[j];                                    \
        float e0 = s1v + s2q.x;                                                  \
        float e1 = s1v + s2q.y;                                                  \
        float e2 = s1v + s2q.z;                                                  \
        float e3 = s1v + s2q.w;                                                  \
        e0 = fmaxf(e0, ALPHA * e0);                                              \
        e1 = fmaxf(e1, ALPHA * e1);                                              \
        e2 = fmaxf(e2, ALPHA * e2);                                              \
        e3 = fmaxf(e3, ALPHA * e3);                                              \
        float p0 = (am.x > 0) ? ex2f(e0 - mi) : 0.f;                             \
        float p1 = (am.y > 0) ? ex2f(e1 - mi) : 0.f;                             \
        float p2 = (am.z > 0) ? ex2f(e2 - mi) : 0.f;                             \
        float p3 = (am.w > 0) ? ex2f(e3 - mi) : 0.f;                             \
        zloc += (p0 + p1) + (p2 + p3);                                           \
        __half2 hA = __floats2half2_rn(p0, p1);                                  \
        __half2 hB = __floats2half2_rn(p2, p3);                                  \
        uint2 hv;                                                                \
        hv.x = *reinterpret_cast<uint32_t*>(&hA);                                \
        hv.y = *reinterpret_cast<uint32_t*>(&hB);                                \
        *(uint2*)(smem + (PB) + r * VST + (jbase + (G) * 4) * 2) = hv;           \
    }

#define ATTN_STAGE(JT, VH_CUR, PB_CUR, PB_NXT)                                   \
    {                                                                            \
        const bool more = ((JT) + 1 < NJ);                                       \
        _Pragma("unroll")                                                        \
        for (int ks = 0; ks < 4; ks++) {                                         \
            const uint32_t kb = ks * 32;                                         \
            uint32_t ah[2][4];                                                   \
            ldsm_x4(ah[0], smem_base + (PB_CUR) + a_row + kb);                   \
            ldsm_x4(ah[1], smem_base + (PB_CUR) + a_row + 16 * VST + kb);        \
            if (more)                                                            \
                P_COMPUTE_G((JT) + 1, ks, PB_NXT);                               \
            _Pragma("unroll")                                                    \
            for (int ntp = 0; ntp < 4; ntp++) {                                  \
                const uint32_t bo = b_row + ntp * 16 * VST + kb;                 \
                uint32_t bh[4];                                                  \
                ldsm_x4(bh, smem_base + (VH_CUR) + bo);                          \
                _Pragma("unroll")                                                \
                for (int mt = 0; mt < 2; mt++) {                                 \
                    mma16816(acc[mt][ntp * 2 + 0], ah[mt], &bh[0]);              \
                    mma16816(acc[mt][ntp * 2 + 1], ah[mt], &bh[2]);              \
                }                                                                \
            }                                                                    \
        }                                                                        \
        if ((JT) + 2 < NJ) {                                                     \
            const int jn2 = ((JT) + 2) * KJ;                                     \
            _Pragma("unroll")                                                    \
            for (int g = 0; g < 4; g++)                                          \
                am_pf[g] = *(const int4*)&adjR[jn2 + jbase + g * 4];             \
        }                                                                        \
        CP_WAIT0();                                                              \
        __syncthreads();                                                         \
        if ((JT) + 2 < NJ)                                                       \
            V_ISSUE((JT) + 2, VH_CUR);                                           \
    }

    // ---- prologue ----
    int4 am_pf[4];
#pragma unroll
    for (int g = 0; g < 4; g++)
        am_pf[g] = *(const int4*)&adjR[jbase + g * 4];
    V_ISSUE(0, SM_VH0);
#pragma unroll
    for (int g = 0; g < 4; g++)
        P_COMPUTE_G(0, g, SM_P0);
    V_ISSUE(1, SM_VH1);
#pragma unroll
    for (int g = 0; g < 4; g++)
        am_pf[g] = *(const int4*)&adjR[KJ + jbase + g * 4];
    CP_WAIT1();
    __syncthreads();

    for (int jt = 0; jt < NJ; jt += 2) {
        ATTN_STAGE(jt,     SM_VH0, SM_P0, SM_P1);
        ATTN_STAGE(jt + 1, SM_VH1, SM_P1, SM_P0);
    }

    // ---- Z reduction ----
    zloc += __shfl_xor_sync(0xffffffffu, zloc, 1);
    zloc += __shfl_xor_sync(0xffffffffu, zloc, 2);
    if ((tid & 3) == 0) *(float*)(smem + SM_ZS + r * 4) = zloc;
    __syncthreads();

    // ---- epilogue: out = acc / Z ----
    const float* Zs = (const float*)(smem + SM_ZS);
    const int ldq = lane >> 2;
#pragma unroll
    for (int mt = 0; mt < 2; mt++) {
        const int row0 = m0w + mt * 16 + ldq;
        const float rz0 = 1.f / Zs[row0];
        const float rz1 = 1.f / Zs[row0 + 8];
        float* __restrict__ o0 = out + ((size_t)b * NN + i0 + row0) * FF;
        float* __restrict__ o1 = o0 + 8 * FF;
#pragma unroll
        for (int nt = 0; nt < 8; nt++) {
            const int col = n0w + nt * 8 + (lane & 3) * 2;
            float2 v0 = make_float2(acc[mt][nt][0] * rz0, acc[mt][nt][1] * rz0);
            float2 v1 = make_float2(acc[mt][nt][2] * rz1, acc[mt][nt][3] * rz1);
            *(float2*)&o0[col] = v0;
            *(float2*)&o1[col] = v1;
        }
    }
}

// ============================================================
// launch
// ============================================================
extern "C" void kernel_launch(void* const* d_in, const int* in_sizes, int n_in,
                              void* d_out, int out_size)
{
    const float* h   = (const float*)d_in[0];
    const int*   adj = (const int*)d_in[1];
    const float* W   = (const float*)d_in[2];
    const float* a   = (const float*)d_in[3];
    float* out = (float*)d_out;

    cudaFuncSetAttribute(gemm_fused_kernel,
                         cudaFuncAttributeMaxDynamicSharedMemorySize, GS_TOTAL);
    cudaFuncSetAttribute(attn_mma_kernel,
                         cudaFuncAttributeMaxDynamicSharedMemorySize, SM_TOTAL);

    gemm_fused_kernel<<<BB * NN / 64, 256, GS_TOTAL>>>(h, W, a);

    dim3 g4(NN / TI, BB);
    attn_mma_kernel<<<g4, 256, SM_TOTAL>>>(adj, out);
}